// round 15
// baseline (speedup 1.0000x reference)
#include <cuda_runtime.h>
#include <cuda_bf16.h>
#include <cstdint>

// Problem constants
#define BB   16
#define CC   768
#define HWs  576
#define NTOK (BB*HWs)          // 9216
#define ELEMS (BB*CC*HWs)      // 7,077,888
#define NLAYER 4

// Scratch (device globals; no allocation allowed)
__device__ float g_cur[ELEMS];
__device__ float g_x5[ELEMS];
__device__ float g_qt[(size_t)NTOK*CC];             // QUERIES: Z_n = M^T x_n + u, tf32 [n][d]
__device__ float g_kt[(size_t)NTOK*CC];             // KEYS: x5 transposed, tf32 [n][c]
__device__ __nv_bfloat16 g_xth[(size_t)NTOK*CC];    // layer input transposed hi
__device__ __nv_bfloat16 g_xtl[(size_t)NTOK*CC];    // lo
__device__ __nv_bfloat16 g_wh[(size_t)NLAYER*CC*CC];    // conv weights hi [o][c]
__device__ __nv_bfloat16 g_wl[(size_t)NLAYER*CC*CC];    // lo
__device__ __nv_bfloat16 g_wth[(size_t)2*NLAYER*CC*CC]; // q|k weights TRANSPOSED hi [c][o]
__device__ __nv_bfloat16 g_wtl[(size_t)2*NLAYER*CC*CC]; // lo
__device__ float g_M[(size_t)NLAYER*CC*CC];         // Mt_i[d][c] = sum_o Wq[o][c]Wk[o][d], tf32
__device__ float g_u[NLAYER*CC];                    // Wk^T bq
__device__ float g_v[NLAYER*CC];                    // Wq^T bk
__device__ float g_r[NTOK];                         // v . x_n per token
__device__ float g_zero[CC];                        // stays zero
__device__ float g_maxpart[BB*NTOK];
__device__ float g_seeds[BB*CC];
__device__ float g_cor[BB*HWs];
__device__ float g_consen[CC];

// ============================ PTX helpers (sm_80+ only) =====================
__device__ __forceinline__ uint32_t smem_u32(const void* p) {
    uint32_t a;
    asm("{ .reg .u64 t; cvta.to.shared.u64 t, %1; cvt.u32.u64 %0, t; }" : "=r"(a) : "l"(p));
    return a;
}
__device__ __forceinline__ void cp16(uint32_t d, const void* s) {
    asm volatile("cp.async.cg.shared.global [%0], [%1], 16;" :: "r"(d), "l"(s));
}
__device__ __forceinline__ void cp_commit() { asm volatile("cp.async.commit_group;"); }
template<int N> __device__ __forceinline__ void cp_wait() {
    asm volatile("cp.async.wait_group %0;" :: "n"(N));
}
__device__ __forceinline__ void ldsm4(uint32_t* r, uint32_t a) {
    asm volatile("ldmatrix.sync.aligned.m8n8.x4.shared.b16 {%0,%1,%2,%3}, [%4];"
                 : "=r"(r[0]), "=r"(r[1]), "=r"(r[2]), "=r"(r[3]) : "r"(a));
}
__device__ __forceinline__ void mma16816(float* d, const uint32_t* a, const uint32_t* b) {
    asm volatile("mma.sync.aligned.m16n8k16.row.col.f32.bf16.bf16.f32 "
                 "{%0,%1,%2,%3}, {%4,%5,%6,%7}, {%8,%9}, {%0,%1,%2,%3};"
                 : "+f"(d[0]), "+f"(d[1]), "+f"(d[2]), "+f"(d[3])
                 : "r"(a[0]), "r"(a[1]), "r"(a[2]), "r"(a[3]), "r"(b[0]), "r"(b[1]));
}
__device__ __forceinline__ uint32_t cvt_tf32(float v) {
    uint32_t r;
    asm volatile("cvt.rna.tf32.f32 %0, %1;" : "=r"(r) : "f"(v));
    return r;
}
__device__ __forceinline__ void mma1688_tf32(float* d, const uint32_t* a,
                                             uint32_t b0, uint32_t b1) {
    asm volatile("mma.sync.aligned.m16n8k8.row.col.f32.tf32.tf32.f32 "
                 "{%0,%1,%2,%3}, {%4,%5,%6,%7}, {%8,%9}, {%0,%1,%2,%3};"
                 : "+f"(d[0]), "+f"(d[1]), "+f"(d[2]), "+f"(d[3])
                 : "r"(a[0]), "r"(a[1]), "r"(a[2]), "r"(a[3]), "r"(b0), "r"(b1));
}

// ---- bf16 GEMM stage: 128(A) x 96(B) x 32k, 80B rows ----
#define TS_STAGE 35840
#define TS_DYN   (3*TS_STAGE)    // 107520  (x2 CTAs = 215040 <= 228KB/SM)

// ---- tf32 stage: 128(A) x 96(B) x 32k fp32, 144B rows ----
#define AT_STAGE 32256
#define AT_DYN   (3*AT_STAGE)    // 96768  (x2 CTAs = 193536 <= 228KB/SM)

// ---------------------------------------------------------------------------
// Conv weight conversion: fp32 [o][c] -> bf16 hi/lo.  grid (CC*CC*NLAYER/256).
// ---------------------------------------------------------------------------
__global__ void convert_w_kernel(const float* __restrict__ cw)
{
    const size_t idx = (size_t)blockIdx.x * 256 + threadIdx.x;
    float v = cw[idx];
    __nv_bfloat16 h = __float2bfloat16(v);
    g_wh[idx] = h;
    g_wl[idx] = __float2bfloat16(v - __bfloat162float(h));
}

// ---------------------------------------------------------------------------
// q/k weight transpose+convert: [o][c] fp32 -> [c][o] bf16 hi/lo.
// grid (24, 24, 8): z = which*NLAYER + layer. block (32,8).
// ---------------------------------------------------------------------------
__global__ void convert_wt_kernel(const float* __restrict__ qw,
                                  const float* __restrict__ kw)
{
    __shared__ float tile[32][33];
    const int z = blockIdx.z;
    const int which = z >> 2;            // 0 q, 1 k
    const int layer = z & 3;
    const float* src = (which ? kw : qw) + (size_t)layer * CC * CC;
    __nv_bfloat16* dh = g_wth + (size_t)which * NLAYER * CC * CC;
    __nv_bfloat16* dl = g_wtl + (size_t)which * NLAYER * CC * CC;
    const int c0 = blockIdx.x * 32;
    const int o0 = blockIdx.y * 32;
    const int tx = threadIdx.x, ty = threadIdx.y;

    #pragma unroll
    for (int j = 0; j < 4; j++) {
        int oo = ty * 4 + j;
        tile[oo][tx] = src[(size_t)(o0 + oo) * CC + c0 + tx];
    }
    __syncthreads();
    #pragma unroll
    for (int j = 0; j < 4; j++) {
        int cc = ty * 4 + j;
        float v = tile[tx][cc];          // = src[o0+tx][c0+cc]
        size_t o = ((size_t)layer * CC + c0 + cc) * CC + o0 + tx;
        __nv_bfloat16 h = __float2bfloat16(v);
        dh[o] = h;
        dl[o] = __float2bfloat16(v - __bfloat162float(h));
    }
}

// ---------------------------------------------------------------------------
// Layer-0 input conversion+transpose: ext [b][c][hw] fp32 -> g_xt [n][c] bf16.
// grid (18, 24, 16), block (32,8).
// ---------------------------------------------------------------------------
__global__ void convert_x_kernel(const float* __restrict__ ext)
{
    __shared__ float tile[32][33];
    const int b = blockIdx.z;
    const float* src = ext + (size_t)b * CC * HWs;
    const int hw0 = blockIdx.x * 32;
    const int c0  = blockIdx.y * 32;
    const int tx = threadIdx.x, ty = threadIdx.y;

    #pragma unroll
    for (int j = 0; j < 4; j++) {
        int c = ty * 4 + j;
        tile[c][tx] = src[(size_t)(c0 + c) * HWs + hw0 + tx];
    }
    __syncthreads();
    #pragma unroll
    for (int j = 0; j < 4; j++) {
        int hwl = ty * 4 + j;
        float v = tile[tx][hwl];
        __nv_bfloat16 h = __float2bfloat16(v);
        __nv_bfloat16 l = __float2bfloat16(v - __bfloat162float(h));
        size_t o = (size_t)(b * HWs + hw0 + hwl) * CC + c0 + tx;
        g_xth[o] = h;
        g_xtl[o] = l;
    }
}

// ---------------------------------------------------------------------------
// u/v build: u_c = sum_o WkT[c][o] bq[o];  v_c = sum_o WqT[c][o] bk[o].
// grid (NLAYER, 2), block 768.
// ---------------------------------------------------------------------------
__global__ void uv_kernel(const float* __restrict__ qb, const float* __restrict__ kb)
{
    const int layer = blockIdx.x;
    const int which = blockIdx.y;        // 0: u (WkT, bq), 1: v (WqT, bk)
    const int c = threadIdx.x;
    const size_t toff = which ? 0 : (size_t)NLAYER * CC * CC;   // u uses k-weights
    const __nv_bfloat16* th = g_wth + toff + ((size_t)layer * CC + c) * CC;
    const __nv_bfloat16* tl = g_wtl + toff + ((size_t)layer * CC + c) * CC;
    const float* bias = (which ? kb : qb) + layer * CC;
    float s = 0.f;
    for (int o = 0; o < CC; o++)
        s = fmaf(__bfloat162float(th[o]) + __bfloat162float(tl[o]), bias[o], s);
    (which ? g_v : g_u)[layer * CC + c] = s;
}

// ---------------------------------------------------------------------------
// r_n = v . x_n (per token, per layer). x lives in g_kt (keys).
// grid 1152, block 256 (warp per n).
// ---------------------------------------------------------------------------
__global__ void r_kernel(const float* __restrict__ v)
{
    const int n = blockIdx.x * 8 + (threadIdx.x >> 5);
    const int lane = threadIdx.x & 31;
    const float* x = g_kt + (size_t)n * CC;
    float s = 0.f;
    for (int c = lane; c < CC; c += 32)
        s = fmaf(x[c], v[c], s);
    s += __shfl_xor_sync(0xffffffffu, s, 16);
    s += __shfl_xor_sync(0xffffffffu, s, 8);
    s += __shfl_xor_sync(0xffffffffu, s, 4);
    s += __shfl_xor_sync(0xffffffffu, s, 2);
    s += __shfl_xor_sync(0xffffffffu, s, 1);
    if (lane == 0) g_r[n] = s;
}

// ---------------------------------------------------------------------------
// Split-bf16 mma.sync GEMM, 128 x 96 per CTA, 256 threads, 2 CTAs/SM,
// 3-stage cp.async ring. out(R, cb) = sum_k A[bb*aB+m0+R'][k] B[bb*nB+n0+cb'][k].
// Writes: optional Y fp32 [b][R][cb] (+residual, conv), optional ft tf32
// transposed [(b*nB+cb)*CC + R] (x5t / Mt).
// ---------------------------------------------------------------------------
__global__ void __launch_bounds__(256, 2) gemm_mma_kernel(
    const __nv_bfloat16* __restrict__ Ah, const __nv_bfloat16* __restrict__ Al,
    const __nv_bfloat16* __restrict__ Bh, const __nv_bfloat16* __restrict__ Bl,
    const float* __restrict__ bias, const float* __restrict__ resid, int residual,
    float* __restrict__ Y, int write_f32, float* __restrict__ ft,
    int aB, int nB)
{
    extern __shared__ __align__(16) char sm[];
    const int t   = threadIdx.x;
    const int wid = t >> 5;
    const int lid = t & 31;
    const int n0  = blockIdx.x * 96;
    const int m0  = blockIdx.y * 128;
    const int b   = blockIdx.z;
    const int warp_m = wid & 3;
    const int warp_n = wid >> 2;
    const uint32_t smbase = smem_u32(sm);
    const size_t arow0 = (size_t)b * aB + m0;
    const size_t brow0 = (size_t)b * nB + n0;

    auto load_stage = [&](int s, int slot) {
        const int k0 = s * 32;
        const uint32_t st = smbase + (uint32_t)slot * TS_STAGE;
        #pragma unroll
        for (int it = 0; it < 2; it++) {
            int jdx = it * 256 + t;
            int row = jdx >> 2, seg = jdx & 3;
            uint32_t d = st + (uint32_t)row * 80u + (uint32_t)seg * 16u;
            cp16(d,          Ah + (arow0 + row) * CC + k0 + seg * 8);
            cp16(d + 10240u, Al + (arow0 + row) * CC + k0 + seg * 8);
        }
        #pragma unroll
        for (int it = 0; it < 2; it++) {
            int jdx = it * 256 + t;
            if (jdx < 384) {
                int row = jdx >> 2, seg = jdx & 3;
                uint32_t d = st + 20480u + (uint32_t)row * 80u + (uint32_t)seg * 16u;
                cp16(d,         Bh + (brow0 + row) * CC + k0 + seg * 8);
                cp16(d + 7680u, Bl + (brow0 + row) * CC + k0 + seg * 8);
            }
        }
    };

    float acc[2][6][4];
    #pragma unroll
    for (int mt = 0; mt < 2; mt++)
        #pragma unroll
        for (int j = 0; j < 6; j++)
            #pragma unroll
            for (int r = 0; r < 4; r++)
                acc[mt][j][r] = 0.f;

    load_stage(0, 0); cp_commit();
    load_stage(1, 1); cp_commit();

    for (int s = 0; s < 24; s++) {
        if (s + 1 < 24) cp_wait<1>(); else cp_wait<0>();
        __syncthreads();
        if (s + 2 < 24) { load_stage(s + 2, (s + 2) % 3); cp_commit(); }

        const uint32_t st = smbase + (uint32_t)(s % 3) * TS_STAGE;
        #pragma unroll
        for (int k16 = 0; k16 < 2; k16++) {
            const int kb = k16 * 16;
            uint32_t bh[12], bl[12];
            #pragma unroll
            for (int nt = 0; nt < 3; nt++) {
                uint32_t ba = st + 20480u
                    + (uint32_t)(warp_n * 48 + nt * 16 + (lid & 7) + ((lid >> 4) & 1) * 8) * 80u
                    + (uint32_t)(kb + ((lid >> 3) & 1) * 8) * 2u;
                ldsm4(&bh[nt * 4], ba);
                ldsm4(&bl[nt * 4], ba + 7680u);
            }
            #pragma unroll
            for (int mt = 0; mt < 2; mt++) {
                uint32_t ah[4], al[4];
                uint32_t aa = st
                    + (uint32_t)(warp_m * 32 + mt * 16 + (lid & 15)) * 80u
                    + (uint32_t)(kb + ((lid >> 4) & 1) * 8) * 2u;
                ldsm4(ah, aa);
                ldsm4(al, aa + 10240u);
                #pragma unroll
                for (int j = 0; j < 6; j++)
                    mma16816(acc[mt][j], ah, &bh[(j >> 1) * 4 + (j & 1) * 2]);
                #pragma unroll
                for (int j = 0; j < 6; j++)
                    mma16816(acc[mt][j], ah, &bl[(j >> 1) * 4 + (j & 1) * 2]);
                #pragma unroll
                for (int j = 0; j < 6; j++)
                    mma16816(acc[mt][j], al, &bh[(j >> 1) * 4 + (j & 1) * 2]);
            }
        }
    }

    // epilogue
    const size_t Yb = (size_t)b * CC * HWs;
    const size_t nb = (size_t)b * nB;
    #pragma unroll
    for (int mt = 0; mt < 2; mt++) {
        int R = m0 + warp_m * 32 + mt * 16 + (lid >> 2);
        float bs0 = bias[R], bs1 = bias[R + 8];
        #pragma unroll
        for (int j = 0; j < 6; j++) {
            int cb = n0 + warp_n * 48 + (j >> 1) * 16 + (j & 1) * 8 + (lid & 3) * 2;
            float v00 = acc[mt][j][0] + bs0, v01 = acc[mt][j][1] + bs0;
            float v10 = acc[mt][j][2] + bs1, v11 = acc[mt][j][3] + bs1;
            if (residual) {
                size_t a0 = Yb + (size_t)R * HWs + cb;
                size_t a1 = a0 + 8 * HWs;
                float2 r0 = *(const float2*)(resid + a0);
                float2 r1 = *(const float2*)(resid + a1);
                v00 += r0.x; v01 += r0.y; v10 += r1.x; v11 += r1.y;
            }
            if (write_f32) {
                size_t a0 = Yb + (size_t)R * HWs + cb;
                size_t a1 = a0 + 8 * HWs;
                *(float2*)(Y + a0) = make_float2(v00, v01);
                *(float2*)(Y + a1) = make_float2(v10, v11);
            }
            if (ft) {
                size_t r0o = (nb + cb) * CC;
                size_t r1o = r0o + CC;
                ft[r0o + R]     = __uint_as_float(cvt_tf32(v00));
                ft[r1o + R]     = __uint_as_float(cvt_tf32(v01));
                ft[r0o + R + 8] = __uint_as_float(cvt_tf32(v10));
                ft[r1o + R + 8] = __uint_as_float(cvt_tf32(v11));
            }
        }
    }
}

// ---------------------------------------------------------------------------
// Z GEMM (tf32 1-pass): Z[n][d] = sum_c Mt[d][c] x_n[c] + u[d]  (queries).
// A = Mt_i (rows d), B = x (g_kt, rows n). grid (96, 6), 256 thr.
// ---------------------------------------------------------------------------
__global__ void __launch_bounds__(256, 2) z_gemm_kernel(
    const float* __restrict__ A, const float* __restrict__ B,
    const float* __restrict__ bias, float* __restrict__ ft)
{
    extern __shared__ __align__(16) char sm[];
    const int t   = threadIdx.x;
    const int wid = t >> 5;
    const int lid = t & 31;
    const int n0  = blockIdx.x * 96;     // token tile
    const int m0  = blockIdx.y * 128;    // d tile
    const int warp_m = wid & 3;
    const int warp_n = wid >> 2;
    const uint32_t smbase = smem_u32(sm);

    uint32_t a_off[2];
    #pragma unroll
    for (int mt = 0; mt < 2; mt++)
        a_off[mt] = (uint32_t)(warp_m * 32 + mt * 16 + ((lid >> 3) & 1) * 8 + (lid & 7)) * 144u
                  + (uint32_t)((lid >> 4) & 1) * 16u;
    uint32_t b_off[3];
    #pragma unroll
    for (int p = 0; p < 3; p++)
        b_off[p] = 18432u
                 + (uint32_t)(warp_n * 48 + (2 * p + ((lid >> 4) & 1)) * 8 + (lid & 7)) * 144u
                 + (uint32_t)((lid >> 3) & 1) * 16u;

    auto load_stage = [&](int s, int slot) {
        const int k0 = s * 32;
        const uint32_t st = smbase + (uint32_t)slot * AT_STAGE;
        #pragma unroll
        for (int it = 0; it < 4; it++) {
            int jdx = it * 256 + t;
            int row = jdx >> 3, seg = jdx & 7;
            uint32_t d = st + (uint32_t)row * 144u + (uint32_t)seg * 16u;
            cp16(d, A + (size_t)(m0 + row) * CC + k0 + seg * 4);
        }
        #pragma unroll
        for (int it = 0; it < 3; it++) {
            int jdx = it * 256 + t;
            int row = jdx >> 3, seg = jdx & 7;
            uint32_t d = st + 18432u + (uint32_t)row * 144u + (uint32_t)seg * 16u;
            cp16(d, B + (size_t)(n0 + row) * CC + k0 + seg * 4);
        }
    };

    float acc[2][6][4];
    #pragma unroll
    for (int mt = 0; mt < 2; mt++)
        #pragma unroll
        for (int j = 0; j < 6; j++)
            #pragma unroll
            for (int r = 0; r < 4; r++)
                acc[mt][j][r] = 0.f;

    load_stage(0, 0); cp_commit();
    load_stage(1, 1); cp_commit();

    for (int s = 0; s < 24; s++) {
        if (s + 1 < 24) cp_wait<1>(); else cp_wait<0>();
        __syncthreads();
        if (s + 2 < 24) { load_stage(s + 2, (s + 2) % 3); cp_commit(); }

        const uint32_t st = smbase + (uint32_t)(s % 3) * AT_STAGE;
        #pragma unroll
        for (int k8 = 0; k8 < 4; k8++) {
            const uint32_t kbyte = (uint32_t)k8 * 32u;
            uint32_t bf[12];
            #pragma unroll
            for (int p = 0; p < 3; p++)
                ldsm4(&bf[p * 4], st + b_off[p] + kbyte);
            #pragma unroll
            for (int mt = 0; mt < 2; mt++) {
                uint32_t af[4];
                ldsm4(af, st + a_off[mt] + kbyte);
                #pragma unroll
                for (int nt = 0; nt < 6; nt++)
                    mma1688_tf32(acc[mt][nt], af, bf[2 * nt], bf[2 * nt + 1]);
            }
        }
    }

    #pragma unroll
    for (int mt = 0; mt < 2; mt++) {
        int R = m0 + warp_m * 32 + mt * 16 + (lid >> 2);
        float u0 = bias[R], u1 = bias[R + 8];
        #pragma unroll
        for (int j = 0; j < 6; j++) {
            int cb = n0 + warp_n * 48 + j * 8 + (lid & 3) * 2;
            size_t r0o = (size_t)cb * CC;
            size_t r1o = r0o + CC;
            ft[r0o + R]     = __uint_as_float(cvt_tf32(acc[mt][j][0] + u0));
            ft[r1o + R]     = __uint_as_float(cvt_tf32(acc[mt][j][1] + u0));
            ft[r0o + R + 8] = __uint_as_float(cvt_tf32(acc[mt][j][2] + u1));
            ft[r1o + R + 8] = __uint_as_float(cvt_tf32(acc[mt][j][3] + u1));
        }
    }
}

// ---------------------------------------------------------------------------
// tf32 attention row-max with LDMATRIX fragment loads.
// Queries = g_qt (Z), keys = g_kt (x). grid (72 m-tiles, 16 bk).
// ---------------------------------------------------------------------------
#define A_NSTG  144              // 6 ct * 24 k-chunks

__global__ void __launch_bounds__(256, 2) attn_mma_kernel()
{
    extern __shared__ __align__(16) char sm[];
    __shared__ float srow[2][128];

    const int t   = threadIdx.x;
    const int wid = t >> 5;
    const int lid = t & 31;
    const int n0  = blockIdx.x * 128;
    const int bk  = blockIdx.y;
    const int warp_m = wid & 3;
    const int warp_n = wid >> 2;
    const uint32_t smbase = smem_u32(sm);

    uint32_t a_off[2];
    #pragma unroll
    for (int mt = 0; mt < 2; mt++)
        a_off[mt] = (uint32_t)(warp_m * 32 + mt * 16 + ((lid >> 3) & 1) * 8 + (lid & 7)) * 144u
                  + (uint32_t)((lid >> 4) & 1) * 16u;
    uint32_t b_off[3];
    #pragma unroll
    for (int p = 0; p < 3; p++)
        b_off[p] = 18432u
                 + (uint32_t)(warp_n * 48 + (2 * p + ((lid >> 4) & 1)) * 8 + (lid & 7)) * 144u
                 + (uint32_t)((lid >> 3) & 1) * 16u;

    auto load_stage = [&](int s, int slot) {
        const int hk0 = (s / 24) * 96;
        const int k0  = (s % 24) * 32;
        const uint32_t st = smbase + (uint32_t)slot * AT_STAGE;
        #pragma unroll
        for (int it = 0; it < 4; it++) {
            int jdx = it * 256 + t;
            int row = jdx >> 3, seg = jdx & 7;
            uint32_t d = st + (uint32_t)row * 144u + (uint32_t)seg * 16u;
            cp16(d, g_qt + (size_t)(n0 + row) * CC + k0 + seg * 4);
        }
        #pragma unroll
        for (int it = 0; it < 3; it++) {
            int jdx = it * 256 + t;
            int row = jdx >> 3, seg = jdx & 7;
            uint32_t d = st + 18432u + (uint32_t)row * 144u + (uint32_t)seg * 16u;
            cp16(d, g_kt + (size_t)(bk * HWs + hk0 + row) * CC + k0 + seg * 4);
        }
    };

    float acc[2][6][4];
    float rm[2][2] = {{-3.402823e38f, -3.402823e38f}, {-3.402823e38f, -3.402823e38f}};

    load_stage(0, 0); cp_commit();
    load_stage(1, 1); cp_commit();

    for (int s = 0; s < A_NSTG; s++) {
        if (s + 1 < A_NSTG) cp_wait<1>(); else cp_wait<0>();
        __syncthreads();
        if (s + 2 < A_NSTG) { load_stage(s + 2, (s + 2) % 3); cp_commit(); }

        if ((s % 24) == 0) {
            #pragma unroll
            for (int mt = 0; mt < 2; mt++)
                #pragma unroll
                for (int j = 0; j < 6; j++)
                    #pragma unroll
                    for (int r = 0; r < 4; r++)
                        acc[mt][j][r] = 0.f;
        }

        const uint32_t st = smbase + (uint32_t)(s % 3) * AT_STAGE;
        #pragma unroll
        for (int k8 = 0; k8 < 4; k8++) {
            const uint32_t kbyte = (uint32_t)k8 * 32u;
            uint32_t bf[12];
            #pragma unroll
            for (int p = 0; p < 3; p++)
                ldsm4(&bf[p * 4], st + b_off[p] + kbyte);
            #pragma unroll
            for (int mt = 0; mt < 2; mt++) {
                uint32_t af[4];
                ldsm4(af, st + a_off[mt] + kbyte);
                #pragma unroll
                for (int nt = 0; nt < 6; nt++)
                    mma1688_tf32(acc[mt][nt], af, bf[2 * nt], bf[2 * nt + 1]);
            }
        }

        if ((s % 24) == 23) {
            #pragma unroll
            for (int mt = 0; mt < 2; mt++) {
                float m0 = -3.402823e38f, m1 = -3.402823e38f;
                #pragma unroll
                for (int j = 0; j < 6; j++) {
                    m0 = fmaxf(m0, fmaxf(acc[mt][j][0], acc[mt][j][1]));
                    m1 = fmaxf(m1, fmaxf(acc[mt][j][2], acc[mt][j][3]));
                }
                m0 = fmaxf(m0, __shfl_xor_sync(0xffffffffu, m0, 1));
                m0 = fmaxf(m0, __shfl_xor_sync(0xffffffffu, m0, 2));
                m1 = fmaxf(m1, __shfl_xor_sync(0xffffffffu, m1, 1));
                m1 = fmaxf(m1, __shfl_xor_sync(0xffffffffu, m1, 2));
                rm[mt][0] = fmaxf(rm[mt][0], m0);
                rm[mt][1] = fmaxf(rm[mt][1], m1);
            }
        }
    }

    __syncthreads();
    if ((lid & 3) == 0) {
        #pragma unroll
        for (int mt = 0; mt < 2; mt++) {
            int r = warp_m * 32 + mt * 16 + (lid >> 2);
            srow[warp_n][r]     = rm[mt][0];
            srow[warp_n][r + 8] = rm[mt][1];
        }
    }
    __syncthreads();
    if (t < 128)
        g_maxpart[bk * NTOK + n0 + t] = fmaxf(srow[0][t], srow[1][t]);
}

// ---------------------------------------------------------------------------
// argmax over hw of [16*r_n + sum_bk maxpart], then seeds. grid=16, block 256.
// ---------------------------------------------------------------------------
__global__ void argmax_seeds_kernel()
{
    const int b = blockIdx.x;
    const int tid = threadIdx.x;
    __shared__ float sv[256];
    __shared__ int   si[256];
    __shared__ int   s_hw;
    __shared__ float s_inv;

    float best = -3.402823e38f;
    int   bidx = 0;
    for (int hw = tid; hw < HWs; hw += 256) {
        float s = 16.f * g_r[b * HWs + hw];
        #pragma unroll
        for (int bk = 0; bk < BB; bk++)
            s += g_maxpart[bk * NTOK + b * HWs + hw];
        if (s > best) { best = s; bidx = hw; }
    }
    sv[tid] = best; si[tid] = bidx;
    __syncthreads();
    for (int s = 128; s > 0; s >>= 1) {
        if (tid < s) {
            if (sv[tid + s] > sv[tid] ||
                (sv[tid + s] == sv[tid] && si[tid + s] < si[tid])) {
                sv[tid] = sv[tid + s];
                si[tid] = si[tid + s];
            }
        }
        __syncthreads();
    }
    if (tid == 0) s_hw = si[0];
    __syncthreads();

    const int hws = s_hw;
    float vv[3];
    float sq = 0.f;
    #pragma unroll
    for (int j = 0; j < 3; j++) {
        int c = tid + j * 256;
        vv[j] = g_x5[(size_t)b * CC * HWs + (size_t)c * HWs + hws];
        sq = fmaf(vv[j], vv[j], sq);
    }
    sv[tid] = sq;
    __syncthreads();
    for (int s = 128; s > 0; s >>= 1) {
        if (tid < s) sv[tid] += sv[tid + s];
        __syncthreads();
    }
    if (tid == 0) s_inv = 1.f / fmaxf(sqrtf(sv[0]), 1e-12f);
    __syncthreads();
    float inv = s_inv;
    #pragma unroll
    for (int j = 0; j < 3; j++)
        g_seeds[b * CC + tid + j * 256] = vv[j] * inv;
}

// ---------------------------------------------------------------------------
// cor[b,hw] = (1/16) * sum_{b'} relu(x5[b,:,hw] . seeds[b',:]) / ||x5[b,:,hw]||
// grid=(16,3), block=192.
// ---------------------------------------------------------------------------
__global__ void cor_kernel()
{
    __shared__ float ss[BB * CC];
    const int b = blockIdx.x;
    for (int i = threadIdx.x; i < BB * CC; i += blockDim.x) ss[i] = g_seeds[i];
    __syncthreads();

    const int hw = blockIdx.y * 192 + threadIdx.x;
    const float* xp = g_x5 + (size_t)b * CC * HWs + hw;
    float acc[BB] = {};
    float sq = 0.f;
    for (int c = 0; c < CC; c++) {
        float v = xp[(size_t)c * HWs];
        sq = fmaf(v, v, sq);
        #pragma unroll
        for (int o = 0; o < BB; o++)
            acc[o] = fmaf(v, ss[o * CC + c], acc[o]);
    }
    float s = 0.f;
    #pragma unroll
    for (int o = 0; o < BB; o++) s += fmaxf(acc[o], 0.f);
    float nrm = fmaxf(sqrtf(sq), 1e-12f);
    g_cor[b * HWs + hw] = s / (16.f * nrm);
}

// Per-batch min-max normalize of cor. grid=16, block=256.
__global__ void minmax_kernel()
{
    const int b = blockIdx.x;
    const int tid = threadIdx.x;
    __shared__ float smn[256], smx[256];
    float mn = 3.402823e38f, mx = -3.402823e38f;
    for (int hw = tid; hw < HWs; hw += 256) {
        float v = g_cor[b * HWs + hw];
        mn = fminf(mn, v);
        mx = fmaxf(mx, v);
    }
    smn[tid] = mn; smx[tid] = mx;
    __syncthreads();
    for (int s = 128; s > 0; s >>= 1) {
        if (tid < s) {
            smn[tid] = fminf(smn[tid], smn[tid + s]);
            smx[tid] = fmaxf(smx[tid], smx[tid + s]);
        }
        __syncthreads();
    }
    float m0 = smn[0];
    float inv = 1.f / (smx[0] - m0 + 1e-12f);
    for (int hw = tid; hw < HWs; hw += 256)
        g_cor[b * HWs + hw] = (g_cor[b * HWs + hw] - m0) * inv;
}

// ---------------------------------------------------------------------------
// apply + transpose-convert: cur = (add_prev?cur:0) + x5*cor, AND write
// cur transposed bf16 hi/lo.  grid (18, 24, 16), block (32,8).
// ---------------------------------------------------------------------------
__global__ void apply_t_kernel(int add_prev)
{
    __shared__ float tile[32][33];
    const int b = blockIdx.z;
    const int hw0 = blockIdx.x * 32;
    const int c0  = blockIdx.y * 32;
    const int tx = threadIdx.x, ty = threadIdx.y;

    const float corv = g_cor[b * HWs + hw0 + tx];
    const size_t base = (size_t)b * CC * HWs;

    #pragma unroll
    for (int j = 0; j < 4; j++) {
        int c = c0 + ty * 4 + j;
        size_t idx = base + (size_t)c * HWs + hw0 + tx;
        float v = g_x5[idx] * corv;
        if (add_prev) v += g_cur[idx];
        g_cur[idx] = v;
        tile[ty * 4 + j][tx] = v;
    }
    __syncthreads();
    #pragma unroll
    for (int j = 0; j < 4; j++) {
        int hwl = ty * 4 + j;
        float v = tile[tx][hwl];
        __nv_bfloat16 h = __float2bfloat16(v);
        __nv_bfloat16 l = __float2bfloat16(v - __bfloat162float(h));
        size_t o = (size_t)(b * HWs + hw0 + hwl) * CC + c0 + tx;
        g_xth[o] = h;
        g_xtl[o] = l;
    }
}

// consen[c] = mean over (b,hw) of cur. grid=768, block=256.
__global__ void consen_kernel()
{
    const int c = blockIdx.x;
    const int tid = threadIdx.x;
    __shared__ float sm[256];
    float s = 0.f;
    for (int b = 0; b < BB; b++) {
        const float* p = g_cur + (size_t)b * CC * HWs + (size_t)c * HWs;
        for (int hw = tid; hw < HWs; hw += 256) s += p[hw];
    }
    sm[tid] = s;
    __syncthreads();
    for (int st = 128; st > 0; st >>= 1) {
        if (tid < st) sm[tid] += sm[tid + st];
        __syncthreads();
    }
    if (tid == 0) g_consen[c] = sm[0] * (1.f / (float)(BB * HWs));
}

__global__ void final_kernel(const float* __restrict__ xin, float* __restrict__ out)
{
    int idx = blockIdx.x * 256 + threadIdx.x;
    int c = (idx / HWs) % CC;
    out[idx] = g_cur[idx] + xin[idx] * g_consen[c];
}

// ---------------------------------------------------------------------------
extern "C" void kernel_launch(void* const* d_in, const int* in_sizes, int n_in,
                              void* d_out, int out_size)
{
    const float* x5      = (const float*)d_in[0];
    const float* conv_w  = (const float*)d_in[1];
    const float* conv_b  = (const float*)d_in[2];
    const float* query_w = (const float*)d_in[3];
    const float* query_b = (const float*)d_in[4];
    const float* key_w   = (const float*)d_in[5];
    const float* key_b   = (const float*)d_in[6];
    float* out = (float*)d_out;

    cudaFuncSetAttribute(attn_mma_kernel,
                         cudaFuncAttributeMaxDynamicSharedMemorySize, AT_DYN);
    cudaFuncSetAttribute(z_gemm_kernel,
                         cudaFuncAttributeMaxDynamicSharedMemorySize, AT_DYN);
    cudaFuncSetAttribute(gemm_mma_kernel,
                         cudaFuncAttributeMaxDynamicSharedMemorySize, TS_DYN);

    __nv_bfloat16 *wh_p, *wl_p, *wth_p, *wtl_p, *xth_p, *xtl_p;
    cudaGetSymbolAddress((void**)&wh_p, g_wh);
    cudaGetSymbolAddress((void**)&wl_p, g_wl);
    cudaGetSymbolAddress((void**)&wth_p, g_wth);
    cudaGetSymbolAddress((void**)&wtl_p, g_wtl);
    cudaGetSymbolAddress((void**)&xth_p, g_xth);
    cudaGetSymbolAddress((void**)&xtl_p, g_xtl);
    float *x5g_p, *cur_p, *qt_p, *kt_p, *M_p, *u_p, *v_p, *zero_p;
    cudaGetSymbolAddress((void**)&x5g_p, g_x5);
    cudaGetSymbolAddress((void**)&cur_p, g_cur);
    cudaGetSymbolAddress((void**)&qt_p, g_qt);
    cudaGetSymbolAddress((void**)&kt_p, g_kt);
    cudaGetSymbolAddress((void**)&M_p, g_M);
    cudaGetSymbolAddress((void**)&u_p, g_u);
    cudaGetSymbolAddress((void**)&v_p, g_v);
    cudaGetSymbolAddress((void**)&zero_p, g_zero);

    const size_t WSZ = (size_t)CC * CC;
    dim3 xgrid(HWs / 32, CC / 32, BB);      // (18, 24, 16)
    dim3 mgrid(HWs / 96, CC / 128, BB);     // (6, 6, 16)
    dim3 mbgrid(CC / 96, CC / 128, NLAYER); // (8, 6, 4)
    dim3 zgrid(NTOK / 96, CC / 128);        // (96, 6)
    dim3 agrid(NTOK / 128, BB);             // (72, 16)
    dim3 cgrid(BB, HWs / 192);              // (16, 3)
    const int egrid = ELEMS / 256;          // 27648

    // -------- once-per-launch precompute --------
    convert_w_kernel<<<NLAYER * CC * CC / 256, 256>>>(conv_w);
    convert_wt_kernel<<<dim3(24, 24, 8), dim3(32, 8)>>>(query_w, key_w);
    // Mt_i[d][c] = sum_o Wq[o][c] Wk[o][d]:  A = WqT (rows c), B = WkT (rows d)
    //   -> out(R=c, cb=d) written to ft[d*CC + c] = Mt[d][c]
    gemm_mma_kernel<<<mbgrid, 256, TS_DYN>>>(
        wth_p, wtl_p,                                 // A = WqT
        wth_p + NLAYER * WSZ, wtl_p + NLAYER * WSZ,   // B = WkT
        zero_p, nullptr, 0, nullptr, 0, M_p, CC, CC);
    uv_kernel<<<dim3(NLAYER, 2), CC>>>(query_b, key_b);
    convert_x_kernel<<<xgrid, dim3(32, 8)>>>(x5);

    for (int i = 0; i < NLAYER; i++) {
        // x5 = conv(cur) + bias + cur   (fp32 Y + tf32 transposed -> g_kt = keys x)
        gemm_mma_kernel<<<mgrid, 256, TS_DYN>>>(
            wh_p + i * WSZ, wl_p + i * WSZ, xth_p, xtl_p,
            conv_b + i * CC, (i == 0) ? x5 : cur_p, 1,
            x5g_p, 1, kt_p, 0, HWs);
        // queries Z_n = Mt x_n + u -> g_qt
        z_gemm_kernel<<<zgrid, 256, AT_DYN>>>(
            M_p + i * WSZ, kt_p, u_p + i * CC, qt_p);
        // r_n = v . x_n
        r_kernel<<<NTOK / 8, 256>>>(v_p + i * CC);
        attn_mma_kernel<<<agrid, 256, AT_DYN>>>();
        argmax_seeds_kernel<<<BB, 256>>>();
        cor_kernel<<<cgrid, 192>>>();
        minmax_kernel<<<BB, 256>>>();
        apply_t_kernel<<<xgrid, dim3(32, 8)>>>(i > 0 ? 1 : 0);
    }
    consen_kernel<<<CC, 256>>>();
    final_kernel<<<egrid, 256>>>(x5, out);
}

// round 16
// speedup vs baseline: 1.1175x; 1.1175x over previous
#include <cuda_runtime.h>
#include <cuda_bf16.h>
#include <cstdint>

// Problem constants
#define BB   16
#define CC   768
#define HWs  576
#define NTOK (BB*HWs)          // 9216
#define ELEMS (BB*CC*HWs)      // 7,077,888
#define NLAYER 4

// Scratch (device globals; no allocation allowed)
__device__ float g_cur[ELEMS];
__device__ float g_x5[ELEMS];
__device__ float g_qt[(size_t)NTOK*CC];             // QUERIES: Z_n = M^T x_n + u, tf32 [n][d]
__device__ float g_kt[(size_t)NTOK*CC];             // KEYS: x5 transposed, tf32 [n][c]
__device__ __nv_bfloat16 g_xth[(size_t)NTOK*CC];    // layer input transposed hi
__device__ __nv_bfloat16 g_xtl[(size_t)NTOK*CC];    // lo
__device__ __nv_bfloat16 g_wh[(size_t)NLAYER*CC*CC];    // conv weights hi [o][c]
__device__ __nv_bfloat16 g_wl[(size_t)NLAYER*CC*CC];    // lo
__device__ __nv_bfloat16 g_wth[(size_t)2*NLAYER*CC*CC]; // q|k weights TRANSPOSED hi [c][o]
__device__ __nv_bfloat16 g_wtl[(size_t)2*NLAYER*CC*CC]; // lo
__device__ float g_M[(size_t)NLAYER*CC*CC];         // Mt_i[d][c] = sum_o Wq[o][c]Wk[o][d], tf32
__device__ float g_u[NLAYER*CC];                    // Wk^T bq
__device__ float g_v[NLAYER*CC];                    // Wq^T bk
__device__ float g_r[NTOK];                         // v . x_n per token
__device__ float g_zero[CC];                        // stays zero
__device__ float g_maxpart[BB*NTOK];
__device__ float g_seeds[BB*CC];
__device__ float g_cor[BB*HWs];
__device__ float g_consen[CC];

// ============================ PTX helpers (sm_80+ only) =====================
__device__ __forceinline__ uint32_t smem_u32(const void* p) {
    uint32_t a;
    asm("{ .reg .u64 t; cvta.to.shared.u64 t, %1; cvt.u32.u64 %0, t; }" : "=r"(a) : "l"(p));
    return a;
}
__device__ __forceinline__ void cp16(uint32_t d, const void* s) {
    asm volatile("cp.async.cg.shared.global [%0], [%1], 16;" :: "r"(d), "l"(s));
}
__device__ __forceinline__ void cp_commit() { asm volatile("cp.async.commit_group;"); }
template<int N> __device__ __forceinline__ void cp_wait() {
    asm volatile("cp.async.wait_group %0;" :: "n"(N));
}
__device__ __forceinline__ void ldsm4(uint32_t* r, uint32_t a) {
    asm volatile("ldmatrix.sync.aligned.m8n8.x4.shared.b16 {%0,%1,%2,%3}, [%4];"
                 : "=r"(r[0]), "=r"(r[1]), "=r"(r[2]), "=r"(r[3]) : "r"(a));
}
__device__ __forceinline__ void mma16816(float* d, const uint32_t* a, const uint32_t* b) {
    asm volatile("mma.sync.aligned.m16n8k16.row.col.f32.bf16.bf16.f32 "
                 "{%0,%1,%2,%3}, {%4,%5,%6,%7}, {%8,%9}, {%0,%1,%2,%3};"
                 : "+f"(d[0]), "+f"(d[1]), "+f"(d[2]), "+f"(d[3])
                 : "r"(a[0]), "r"(a[1]), "r"(a[2]), "r"(a[3]), "r"(b[0]), "r"(b[1]));
}
__device__ __forceinline__ uint32_t cvt_tf32(float v) {
    uint32_t r;
    asm volatile("cvt.rna.tf32.f32 %0, %1;" : "=r"(r) : "f"(v));
    return r;
}
__device__ __forceinline__ void mma1688_tf32(float* d, const uint32_t* a,
                                             uint32_t b0, uint32_t b1) {
    asm volatile("mma.sync.aligned.m16n8k8.row.col.f32.tf32.tf32.f32 "
                 "{%0,%1,%2,%3}, {%4,%5,%6,%7}, {%8,%9}, {%0,%1,%2,%3};"
                 : "+f"(d[0]), "+f"(d[1]), "+f"(d[2]), "+f"(d[3])
                 : "r"(a[0]), "r"(a[1]), "r"(a[2]), "r"(a[3]), "r"(b0), "r"(b1));
}

// ---- bf16 GEMM stage: 128(A) x 96(B) x 32k, 80B rows ----
#define TS_STAGE 35840
#define TS_DYN   (3*TS_STAGE)    // 107520  (x2 CTAs = 215040 <= 228KB/SM)

// ---- tf32 stage: 128(A) x 96(B) x 32k fp32, 144B rows ----
#define AT_STAGE 32256
#define AT_DYN   (3*AT_STAGE)    // 96768  (x2 CTAs = 193536 <= 228KB/SM)

// ---------------------------------------------------------------------------
// Conv weight conversion: fp32 [o][c] -> bf16 hi/lo.  grid (CC*CC*NLAYER/256).
// ---------------------------------------------------------------------------
__global__ void convert_w_kernel(const float* __restrict__ cw)
{
    const size_t idx = (size_t)blockIdx.x * 256 + threadIdx.x;
    float v = cw[idx];
    __nv_bfloat16 h = __float2bfloat16(v);
    g_wh[idx] = h;
    g_wl[idx] = __float2bfloat16(v - __bfloat162float(h));
}

// ---------------------------------------------------------------------------
// q/k weight transpose+convert: [o][c] fp32 -> [c][o] bf16 hi/lo.
// grid (24, 24, 8): z = which*NLAYER + layer. block (32,8).
// ---------------------------------------------------------------------------
__global__ void convert_wt_kernel(const float* __restrict__ qw,
                                  const float* __restrict__ kw)
{
    __shared__ float tile[32][33];
    const int z = blockIdx.z;
    const int which = z >> 2;            // 0 q, 1 k
    const int layer = z & 3;
    const float* src = (which ? kw : qw) + (size_t)layer * CC * CC;
    __nv_bfloat16* dh = g_wth + (size_t)which * NLAYER * CC * CC;
    __nv_bfloat16* dl = g_wtl + (size_t)which * NLAYER * CC * CC;
    const int c0 = blockIdx.x * 32;
    const int o0 = blockIdx.y * 32;
    const int tx = threadIdx.x, ty = threadIdx.y;

    #pragma unroll
    for (int j = 0; j < 4; j++) {
        int oo = ty * 4 + j;
        tile[oo][tx] = src[(size_t)(o0 + oo) * CC + c0 + tx];
    }
    __syncthreads();
    #pragma unroll
    for (int j = 0; j < 4; j++) {
        int cc = ty * 4 + j;
        float v = tile[tx][cc];          // = src[o0+tx][c0+cc]
        size_t o = ((size_t)layer * CC + c0 + cc) * CC + o0 + tx;
        __nv_bfloat16 h = __float2bfloat16(v);
        dh[o] = h;
        dl[o] = __float2bfloat16(v - __bfloat162float(h));
    }
}

// ---------------------------------------------------------------------------
// Layer-0 input conversion+transpose: ext [b][c][hw] fp32 -> g_xt [n][c] bf16.
// grid (18, 24, 16), block (32,8).
// ---------------------------------------------------------------------------
__global__ void convert_x_kernel(const float* __restrict__ ext)
{
    __shared__ float tile[32][33];
    const int b = blockIdx.z;
    const float* src = ext + (size_t)b * CC * HWs;
    const int hw0 = blockIdx.x * 32;
    const int c0  = blockIdx.y * 32;
    const int tx = threadIdx.x, ty = threadIdx.y;

    #pragma unroll
    for (int j = 0; j < 4; j++) {
        int c = ty * 4 + j;
        tile[c][tx] = src[(size_t)(c0 + c) * HWs + hw0 + tx];
    }
    __syncthreads();
    #pragma unroll
    for (int j = 0; j < 4; j++) {
        int hwl = ty * 4 + j;
        float v = tile[tx][hwl];
        __nv_bfloat16 h = __float2bfloat16(v);
        __nv_bfloat16 l = __float2bfloat16(v - __bfloat162float(h));
        size_t o = (size_t)(b * HWs + hw0 + hwl) * CC + c0 + tx;
        g_xth[o] = h;
        g_xtl[o] = l;
    }
}

// ---------------------------------------------------------------------------
// u/v build, warp-parallel: one warp per (which, layer*CC + c).
// u_c = sum_o WkT[c][o] bq[o];  v_c = sum_o WqT[c][o] bk[o].
// grid (384, 2), block 256 (8 warps).
// ---------------------------------------------------------------------------
__global__ void uv_kernel(const float* __restrict__ qb, const float* __restrict__ kb)
{
    const int which = blockIdx.y;        // 0: u (WkT, bq), 1: v (WqT, bk)
    const int idx = blockIdx.x * 8 + (threadIdx.x >> 5);   // 0..NLAYER*CC-1
    const int lane = threadIdx.x & 31;
    const int layer = idx / CC;
    const int c = idx % CC;
    const size_t toff = which ? 0 : (size_t)NLAYER * CC * CC;   // u uses k-weights
    const __nv_bfloat16* th = g_wth + toff + ((size_t)layer * CC + c) * CC;
    const __nv_bfloat16* tl = g_wtl + toff + ((size_t)layer * CC + c) * CC;
    const float* bias = (which ? kb : qb) + layer * CC;
    float s = 0.f;
    for (int o = lane; o < CC; o += 32)
        s = fmaf(__bfloat162float(th[o]) + __bfloat162float(tl[o]), bias[o], s);
    s += __shfl_xor_sync(0xffffffffu, s, 16);
    s += __shfl_xor_sync(0xffffffffu, s, 8);
    s += __shfl_xor_sync(0xffffffffu, s, 4);
    s += __shfl_xor_sync(0xffffffffu, s, 2);
    s += __shfl_xor_sync(0xffffffffu, s, 1);
    if (lane == 0) (which ? g_v : g_u)[idx] = s;
}

// ---------------------------------------------------------------------------
// r_n = v . x_n (per token, per layer). x lives in g_kt (keys).
// grid 1152, block 256 (warp per n).
// ---------------------------------------------------------------------------
__global__ void r_kernel(const float* __restrict__ v)
{
    const int n = blockIdx.x * 8 + (threadIdx.x >> 5);
    const int lane = threadIdx.x & 31;
    const float* x = g_kt + (size_t)n * CC;
    float s = 0.f;
    for (int c = lane; c < CC; c += 32)
        s = fmaf(x[c], v[c], s);
    s += __shfl_xor_sync(0xffffffffu, s, 16);
    s += __shfl_xor_sync(0xffffffffu, s, 8);
    s += __shfl_xor_sync(0xffffffffu, s, 4);
    s += __shfl_xor_sync(0xffffffffu, s, 2);
    s += __shfl_xor_sync(0xffffffffu, s, 1);
    if (lane == 0) g_r[n] = s;
}

// ---------------------------------------------------------------------------
// Split-bf16 mma.sync GEMM, 128 x 96 per CTA, 256 threads, 2 CTAs/SM,
// 3-stage cp.async ring. out(R, cb) = sum_k A[bb*aB+m0+R'][k] B[bb*nB+n0+cb'][k].
// Writes: optional Y fp32 [b][R][cb] (+residual, conv), optional ft tf32
// transposed [(b*nB+cb)*CC + R] (x5t / Mt).
// ---------------------------------------------------------------------------
__global__ void __launch_bounds__(256, 2) gemm_mma_kernel(
    const __nv_bfloat16* __restrict__ Ah, const __nv_bfloat16* __restrict__ Al,
    const __nv_bfloat16* __restrict__ Bh, const __nv_bfloat16* __restrict__ Bl,
    const float* __restrict__ bias, const float* __restrict__ resid, int residual,
    float* __restrict__ Y, int write_f32, float* __restrict__ ft,
    int aB, int nB)
{
    extern __shared__ __align__(16) char sm[];
    const int t   = threadIdx.x;
    const int wid = t >> 5;
    const int lid = t & 31;
    const int n0  = blockIdx.x * 96;
    const int m0  = blockIdx.y * 128;
    const int b   = blockIdx.z;
    const int warp_m = wid & 3;
    const int warp_n = wid >> 2;
    const uint32_t smbase = smem_u32(sm);
    const size_t arow0 = (size_t)b * aB + m0;
    const size_t brow0 = (size_t)b * nB + n0;

    auto load_stage = [&](int s, int slot) {
        const int k0 = s * 32;
        const uint32_t st = smbase + (uint32_t)slot * TS_STAGE;
        #pragma unroll
        for (int it = 0; it < 2; it++) {
            int jdx = it * 256 + t;
            int row = jdx >> 2, seg = jdx & 3;
            uint32_t d = st + (uint32_t)row * 80u + (uint32_t)seg * 16u;
            cp16(d,          Ah + (arow0 + row) * CC + k0 + seg * 8);
            cp16(d + 10240u, Al + (arow0 + row) * CC + k0 + seg * 8);
        }
        #pragma unroll
        for (int it = 0; it < 2; it++) {
            int jdx = it * 256 + t;
            if (jdx < 384) {
                int row = jdx >> 2, seg = jdx & 3;
                uint32_t d = st + 20480u + (uint32_t)row * 80u + (uint32_t)seg * 16u;
                cp16(d,         Bh + (brow0 + row) * CC + k0 + seg * 8);
                cp16(d + 7680u, Bl + (brow0 + row) * CC + k0 + seg * 8);
            }
        }
    };

    float acc[2][6][4];
    #pragma unroll
    for (int mt = 0; mt < 2; mt++)
        #pragma unroll
        for (int j = 0; j < 6; j++)
            #pragma unroll
            for (int r = 0; r < 4; r++)
                acc[mt][j][r] = 0.f;

    load_stage(0, 0); cp_commit();
    load_stage(1, 1); cp_commit();

    for (int s = 0; s < 24; s++) {
        if (s + 1 < 24) cp_wait<1>(); else cp_wait<0>();
        __syncthreads();
        if (s + 2 < 24) { load_stage(s + 2, (s + 2) % 3); cp_commit(); }

        const uint32_t st = smbase + (uint32_t)(s % 3) * TS_STAGE;
        #pragma unroll
        for (int k16 = 0; k16 < 2; k16++) {
            const int kb = k16 * 16;
            uint32_t bh[12], bl[12];
            #pragma unroll
            for (int nt = 0; nt < 3; nt++) {
                uint32_t ba = st + 20480u
                    + (uint32_t)(warp_n * 48 + nt * 16 + (lid & 7) + ((lid >> 4) & 1) * 8) * 80u
                    + (uint32_t)(kb + ((lid >> 3) & 1) * 8) * 2u;
                ldsm4(&bh[nt * 4], ba);
                ldsm4(&bl[nt * 4], ba + 7680u);
            }
            #pragma unroll
            for (int mt = 0; mt < 2; mt++) {
                uint32_t ah[4], al[4];
                uint32_t aa = st
                    + (uint32_t)(warp_m * 32 + mt * 16 + (lid & 15)) * 80u
                    + (uint32_t)(kb + ((lid >> 4) & 1) * 8) * 2u;
                ldsm4(ah, aa);
                ldsm4(al, aa + 10240u);
                #pragma unroll
                for (int j = 0; j < 6; j++)
                    mma16816(acc[mt][j], ah, &bh[(j >> 1) * 4 + (j & 1) * 2]);
                #pragma unroll
                for (int j = 0; j < 6; j++)
                    mma16816(acc[mt][j], ah, &bl[(j >> 1) * 4 + (j & 1) * 2]);
                #pragma unroll
                for (int j = 0; j < 6; j++)
                    mma16816(acc[mt][j], al, &bh[(j >> 1) * 4 + (j & 1) * 2]);
            }
        }
    }

    // epilogue
    const size_t Yb = (size_t)b * CC * HWs;
    const size_t nb = (size_t)b * nB;
    #pragma unroll
    for (int mt = 0; mt < 2; mt++) {
        int R = m0 + warp_m * 32 + mt * 16 + (lid >> 2);
        float bs0 = bias[R], bs1 = bias[R + 8];
        #pragma unroll
        for (int j = 0; j < 6; j++) {
            int cb = n0 + warp_n * 48 + (j >> 1) * 16 + (j & 1) * 8 + (lid & 3) * 2;
            float v00 = acc[mt][j][0] + bs0, v01 = acc[mt][j][1] + bs0;
            float v10 = acc[mt][j][2] + bs1, v11 = acc[mt][j][3] + bs1;
            if (residual) {
                size_t a0 = Yb + (size_t)R * HWs + cb;
                size_t a1 = a0 + 8 * HWs;
                float2 r0 = *(const float2*)(resid + a0);
                float2 r1 = *(const float2*)(resid + a1);
                v00 += r0.x; v01 += r0.y; v10 += r1.x; v11 += r1.y;
            }
            if (write_f32) {
                size_t a0 = Yb + (size_t)R * HWs + cb;
                size_t a1 = a0 + 8 * HWs;
                *(float2*)(Y + a0) = make_float2(v00, v01);
                *(float2*)(Y + a1) = make_float2(v10, v11);
            }
            if (ft) {
                size_t r0o = (nb + cb) * CC;
                size_t r1o = r0o + CC;
                ft[r0o + R]     = __uint_as_float(cvt_tf32(v00));
                ft[r1o + R]     = __uint_as_float(cvt_tf32(v01));
                ft[r0o + R + 8] = __uint_as_float(cvt_tf32(v10));
                ft[r1o + R + 8] = __uint_as_float(cvt_tf32(v11));
            }
        }
    }
}

// ---------------------------------------------------------------------------
// Z GEMM (tf32 1-pass): Z[n][d] = sum_c Mt[d][c] x_n[c] + u[d]  (queries).
// A = Mt_i (rows d), B = x (g_kt, rows n). grid (96, 6), 256 thr.
// ---------------------------------------------------------------------------
__global__ void __launch_bounds__(256, 2) z_gemm_kernel(
    const float* __restrict__ A, const float* __restrict__ B,
    const float* __restrict__ bias, float* __restrict__ ft)
{
    extern __shared__ __align__(16) char sm[];
    const int t   = threadIdx.x;
    const int wid = t >> 5;
    const int lid = t & 31;
    const int n0  = blockIdx.x * 96;     // token tile
    const int m0  = blockIdx.y * 128;    // d tile
    const int warp_m = wid & 3;
    const int warp_n = wid >> 2;
    const uint32_t smbase = smem_u32(sm);

    uint32_t a_off[2];
    #pragma unroll
    for (int mt = 0; mt < 2; mt++)
        a_off[mt] = (uint32_t)(warp_m * 32 + mt * 16 + ((lid >> 3) & 1) * 8 + (lid & 7)) * 144u
                  + (uint32_t)((lid >> 4) & 1) * 16u;
    uint32_t b_off[3];
    #pragma unroll
    for (int p = 0; p < 3; p++)
        b_off[p] = 18432u
                 + (uint32_t)(warp_n * 48 + (2 * p + ((lid >> 4) & 1)) * 8 + (lid & 7)) * 144u
                 + (uint32_t)((lid >> 3) & 1) * 16u;

    auto load_stage = [&](int s, int slot) {
        const int k0 = s * 32;
        const uint32_t st = smbase + (uint32_t)slot * AT_STAGE;
        #pragma unroll
        for (int it = 0; it < 4; it++) {
            int jdx = it * 256 + t;
            int row = jdx >> 3, seg = jdx & 7;
            uint32_t d = st + (uint32_t)row * 144u + (uint32_t)seg * 16u;
            cp16(d, A + (size_t)(m0 + row) * CC + k0 + seg * 4);
        }
        #pragma unroll
        for (int it = 0; it < 3; it++) {
            int jdx = it * 256 + t;
            int row = jdx >> 3, seg = jdx & 7;
            uint32_t d = st + 18432u + (uint32_t)row * 144u + (uint32_t)seg * 16u;
            cp16(d, B + (size_t)(n0 + row) * CC + k0 + seg * 4);
        }
    };

    float acc[2][6][4];
    #pragma unroll
    for (int mt = 0; mt < 2; mt++)
        #pragma unroll
        for (int j = 0; j < 6; j++)
            #pragma unroll
            for (int r = 0; r < 4; r++)
                acc[mt][j][r] = 0.f;

    load_stage(0, 0); cp_commit();
    load_stage(1, 1); cp_commit();

    for (int s = 0; s < 24; s++) {
        if (s + 1 < 24) cp_wait<1>(); else cp_wait<0>();
        __syncthreads();
        if (s + 2 < 24) { load_stage(s + 2, (s + 2) % 3); cp_commit(); }

        const uint32_t st = smbase + (uint32_t)(s % 3) * AT_STAGE;
        #pragma unroll
        for (int k8 = 0; k8 < 4; k8++) {
            const uint32_t kbyte = (uint32_t)k8 * 32u;
            uint32_t bf[12];
            #pragma unroll
            for (int p = 0; p < 3; p++)
                ldsm4(&bf[p * 4], st + b_off[p] + kbyte);
            #pragma unroll
            for (int mt = 0; mt < 2; mt++) {
                uint32_t af[4];
                ldsm4(af, st + a_off[mt] + kbyte);
                #pragma unroll
                for (int nt = 0; nt < 6; nt++)
                    mma1688_tf32(acc[mt][nt], af, bf[2 * nt], bf[2 * nt + 1]);
            }
        }
    }

    #pragma unroll
    for (int mt = 0; mt < 2; mt++) {
        int R = m0 + warp_m * 32 + mt * 16 + (lid >> 2);
        float u0 = bias[R], u1 = bias[R + 8];
        #pragma unroll
        for (int j = 0; j < 6; j++) {
            int cb = n0 + warp_n * 48 + j * 8 + (lid & 3) * 2;
            size_t r0o = (size_t)cb * CC;
            size_t r1o = r0o + CC;
            ft[r0o + R]     = __uint_as_float(cvt_tf32(acc[mt][j][0] + u0));
            ft[r1o + R]     = __uint_as_float(cvt_tf32(acc[mt][j][1] + u0));
            ft[r0o + R + 8] = __uint_as_float(cvt_tf32(acc[mt][j][2] + u1));
            ft[r1o + R + 8] = __uint_as_float(cvt_tf32(acc[mt][j][3] + u1));
        }
    }
}

// ---------------------------------------------------------------------------
// tf32 attention row-max with LDMATRIX fragment loads.
// Queries = g_qt (Z), keys = g_kt (x). grid (72 m-tiles, 16 bk).
// ---------------------------------------------------------------------------
#define A_NSTG  144              // 6 ct * 24 k-chunks

__global__ void __launch_bounds__(256, 2) attn_mma_kernel()
{
    extern __shared__ __align__(16) char sm[];
    __shared__ float srow[2][128];

    const int t   = threadIdx.x;
    const int wid = t >> 5;
    const int lid = t & 31;
    const int n0  = blockIdx.x * 128;
    const int bk  = blockIdx.y;
    const int warp_m = wid & 3;
    const int warp_n = wid >> 2;
    const uint32_t smbase = smem_u32(sm);

    uint32_t a_off[2];
    #pragma unroll
    for (int mt = 0; mt < 2; mt++)
        a_off[mt] = (uint32_t)(warp_m * 32 + mt * 16 + ((lid >> 3) & 1) * 8 + (lid & 7)) * 144u
                  + (uint32_t)((lid >> 4) & 1) * 16u;
    uint32_t b_off[3];
    #pragma unroll
    for (int p = 0; p < 3; p++)
        b_off[p] = 18432u
                 + (uint32_t)(warp_n * 48 + (2 * p + ((lid >> 4) & 1)) * 8 + (lid & 7)) * 144u
                 + (uint32_t)((lid >> 3) & 1) * 16u;

    auto load_stage = [&](int s, int slot) {
        const int hk0 = (s / 24) * 96;
        const int k0  = (s % 24) * 32;
        const uint32_t st = smbase + (uint32_t)slot * AT_STAGE;
        #pragma unroll
        for (int it = 0; it < 4; it++) {
            int jdx = it * 256 + t;
            int row = jdx >> 3, seg = jdx & 7;
            uint32_t d = st + (uint32_t)row * 144u + (uint32_t)seg * 16u;
            cp16(d, g_qt + (size_t)(n0 + row) * CC + k0 + seg * 4);
        }
        #pragma unroll
        for (int it = 0; it < 3; it++) {
            int jdx = it * 256 + t;
            int row = jdx >> 3, seg = jdx & 7;
            uint32_t d = st + 18432u + (uint32_t)row * 144u + (uint32_t)seg * 16u;
            cp16(d, g_kt + (size_t)(bk * HWs + hk0 + row) * CC + k0 + seg * 4);
        }
    };

    float acc[2][6][4];
    float rm[2][2] = {{-3.402823e38f, -3.402823e38f}, {-3.402823e38f, -3.402823e38f}};

    load_stage(0, 0); cp_commit();
    load_stage(1, 1); cp_commit();

    for (int s = 0; s < A_NSTG; s++) {
        if (s + 1 < A_NSTG) cp_wait<1>(); else cp_wait<0>();
        __syncthreads();
        if (s + 2 < A_NSTG) { load_stage(s + 2, (s + 2) % 3); cp_commit(); }

        if ((s % 24) == 0) {
            #pragma unroll
            for (int mt = 0; mt < 2; mt++)
                #pragma unroll
                for (int j = 0; j < 6; j++)
                    #pragma unroll
                    for (int r = 0; r < 4; r++)
                        acc[mt][j][r] = 0.f;
        }

        const uint32_t st = smbase + (uint32_t)(s % 3) * AT_STAGE;
        #pragma unroll
        for (int k8 = 0; k8 < 4; k8++) {
            const uint32_t kbyte = (uint32_t)k8 * 32u;
            uint32_t bf[12];
            #pragma unroll
            for (int p = 0; p < 3; p++)
                ldsm4(&bf[p * 4], st + b_off[p] + kbyte);
            #pragma unroll
            for (int mt = 0; mt < 2; mt++) {
                uint32_t af[4];
                ldsm4(af, st + a_off[mt] + kbyte);
                #pragma unroll
                for (int nt = 0; nt < 6; nt++)
                    mma1688_tf32(acc[mt][nt], af, bf[2 * nt], bf[2 * nt + 1]);
            }
        }

        if ((s % 24) == 23) {
            #pragma unroll
            for (int mt = 0; mt < 2; mt++) {
                float m0 = -3.402823e38f, m1 = -3.402823e38f;
                #pragma unroll
                for (int j = 0; j < 6; j++) {
                    m0 = fmaxf(m0, fmaxf(acc[mt][j][0], acc[mt][j][1]));
                    m1 = fmaxf(m1, fmaxf(acc[mt][j][2], acc[mt][j][3]));
                }
                m0 = fmaxf(m0, __shfl_xor_sync(0xffffffffu, m0, 1));
                m0 = fmaxf(m0, __shfl_xor_sync(0xffffffffu, m0, 2));
                m1 = fmaxf(m1, __shfl_xor_sync(0xffffffffu, m1, 1));
                m1 = fmaxf(m1, __shfl_xor_sync(0xffffffffu, m1, 2));
                rm[mt][0] = fmaxf(rm[mt][0], m0);
                rm[mt][1] = fmaxf(rm[mt][1], m1);
            }
        }
    }

    __syncthreads();
    if ((lid & 3) == 0) {
        #pragma unroll
        for (int mt = 0; mt < 2; mt++) {
            int r = warp_m * 32 + mt * 16 + (lid >> 2);
            srow[warp_n][r]     = rm[mt][0];
            srow[warp_n][r + 8] = rm[mt][1];
        }
    }
    __syncthreads();
    if (t < 128)
        g_maxpart[bk * NTOK + n0 + t] = fmaxf(srow[0][t], srow[1][t]);
}

// ---------------------------------------------------------------------------
// argmax over hw of [16*r_n + sum_bk maxpart], then seeds. grid=16, block 256.
// ---------------------------------------------------------------------------
__global__ void argmax_seeds_kernel()
{
    const int b = blockIdx.x;
    const int tid = threadIdx.x;
    __shared__ float sv[256];
    __shared__ int   si[256];
    __shared__ int   s_hw;
    __shared__ float s_inv;

    float best = -3.402823e38f;
    int   bidx = 0;
    for (int hw = tid; hw < HWs; hw += 256) {
        float s = 16.f * g_r[b * HWs + hw];
        #pragma unroll
        for (int bk = 0; bk < BB; bk++)
            s += g_maxpart[bk * NTOK + b * HWs + hw];
        if (s > best) { best = s; bidx = hw; }
    }
    sv[tid] = best; si[tid] = bidx;
    __syncthreads();
    for (int s = 128; s > 0; s >>= 1) {
        if (tid < s) {
            if (sv[tid + s] > sv[tid] ||
                (sv[tid + s] == sv[tid] && si[tid + s] < si[tid])) {
                sv[tid] = sv[tid + s];
                si[tid] = si[tid + s];
            }
        }
        __syncthreads();
    }
    if (tid == 0) s_hw = si[0];
    __syncthreads();

    const int hws = s_hw;
    float vv[3];
    float sq = 0.f;
    #pragma unroll
    for (int j = 0; j < 3; j++) {
        int c = tid + j * 256;
        vv[j] = g_x5[(size_t)b * CC * HWs + (size_t)c * HWs + hws];
        sq = fmaf(vv[j], vv[j], sq);
    }
    sv[tid] = sq;
    __syncthreads();
    for (int s = 128; s > 0; s >>= 1) {
        if (tid < s) sv[tid] += sv[tid + s];
        __syncthreads();
    }
    if (tid == 0) s_inv = 1.f / fmaxf(sqrtf(sv[0]), 1e-12f);
    __syncthreads();
    float inv = s_inv;
    #pragma unroll
    for (int j = 0; j < 3; j++)
        g_seeds[b * CC + tid + j * 256] = vv[j] * inv;
}

// ---------------------------------------------------------------------------
// cor[b,hw] = (1/16) * sum_{b'} relu(x5[b,:,hw] . seeds[b',:]) / ||x5[b,:,hw]||
// grid=(16,3), block=192.
// ---------------------------------------------------------------------------
__global__ void cor_kernel()
{
    __shared__ float ss[BB * CC];
    const int b = blockIdx.x;
    for (int i = threadIdx.x; i < BB * CC; i += blockDim.x) ss[i] = g_seeds[i];
    __syncthreads();

    const int hw = blockIdx.y * 192 + threadIdx.x;
    const float* xp = g_x5 + (size_t)b * CC * HWs + hw;
    float acc[BB] = {};
    float sq = 0.f;
    for (int c = 0; c < CC; c++) {
        float v = xp[(size_t)c * HWs];
        sq = fmaf(v, v, sq);
        #pragma unroll
        for (int o = 0; o < BB; o++)
            acc[o] = fmaf(v, ss[o * CC + c], acc[o]);
    }
    float s = 0.f;
    #pragma unroll
    for (int o = 0; o < BB; o++) s += fmaxf(acc[o], 0.f);
    float nrm = fmaxf(sqrtf(sq), 1e-12f);
    g_cor[b * HWs + hw] = s / (16.f * nrm);
}

// Per-batch min-max normalize of cor. grid=16, block=256.
__global__ void minmax_kernel()
{
    const int b = blockIdx.x;
    const int tid = threadIdx.x;
    __shared__ float smn[256], smx[256];
    float mn = 3.402823e38f, mx = -3.402823e38f;
    for (int hw = tid; hw < HWs; hw += 256) {
        float v = g_cor[b * HWs + hw];
        mn = fminf(mn, v);
        mx = fmaxf(mx, v);
    }
    smn[tid] = mn; smx[tid] = mx;
    __syncthreads();
    for (int s = 128; s > 0; s >>= 1) {
        if (tid < s) {
            smn[tid] = fminf(smn[tid], smn[tid + s]);
            smx[tid] = fmaxf(smx[tid], smx[tid + s]);
        }
        __syncthreads();
    }
    float m0 = smn[0];
    float inv = 1.f / (smx[0] - m0 + 1e-12f);
    for (int hw = tid; hw < HWs; hw += 256)
        g_cor[b * HWs + hw] = (g_cor[b * HWs + hw] - m0) * inv;
}

// ---------------------------------------------------------------------------
// apply + transpose-convert: cur = (add_prev?cur:0) + x5*cor, AND write
// cur transposed bf16 hi/lo.  grid (18, 24, 16), block (32,8).
// ---------------------------------------------------------------------------
__global__ void apply_t_kernel(int add_prev)
{
    __shared__ float tile[32][33];
    const int b = blockIdx.z;
    const int hw0 = blockIdx.x * 32;
    const int c0  = blockIdx.y * 32;
    const int tx = threadIdx.x, ty = threadIdx.y;

    const float corv = g_cor[b * HWs + hw0 + tx];
    const size_t base = (size_t)b * CC * HWs;

    #pragma unroll
    for (int j = 0; j < 4; j++) {
        int c = c0 + ty * 4 + j;
        size_t idx = base + (size_t)c * HWs + hw0 + tx;
        float v = g_x5[idx] * corv;
        if (add_prev) v += g_cur[idx];
        g_cur[idx] = v;
        tile[ty * 4 + j][tx] = v;
    }
    __syncthreads();
    #pragma unroll
    for (int j = 0; j < 4; j++) {
        int hwl = ty * 4 + j;
        float v = tile[tx][hwl];
        __nv_bfloat16 h = __float2bfloat16(v);
        __nv_bfloat16 l = __float2bfloat16(v - __bfloat162float(h));
        size_t o = (size_t)(b * HWs + hw0 + hwl) * CC + c0 + tx;
        g_xth[o] = h;
        g_xtl[o] = l;
    }
}

// consen[c] = mean over (b,hw) of cur. grid=768, block=256.
__global__ void consen_kernel()
{
    const int c = blockIdx.x;
    const int tid = threadIdx.x;
    __shared__ float sm[256];
    float s = 0.f;
    for (int b = 0; b < BB; b++) {
        const float* p = g_cur + (size_t)b * CC * HWs + (size_t)c * HWs;
        for (int hw = tid; hw < HWs; hw += 256) s += p[hw];
    }
    sm[tid] = s;
    __syncthreads();
    for (int st = 128; st > 0; st >>= 1) {
        if (tid < st) sm[tid] += sm[tid + st];
        __syncthreads();
    }
    if (tid == 0) g_consen[c] = sm[0] * (1.f / (float)(BB * HWs));
}

__global__ void final_kernel(const float* __restrict__ xin, float* __restrict__ out)
{
    int idx = blockIdx.x * 256 + threadIdx.x;
    int c = (idx / HWs) % CC;
    out[idx] = g_cur[idx] + xin[idx] * g_consen[c];
}

// ---------------------------------------------------------------------------
extern "C" void kernel_launch(void* const* d_in, const int* in_sizes, int n_in,
                              void* d_out, int out_size)
{
    const float* x5      = (const float*)d_in[0];
    const float* conv_w  = (const float*)d_in[1];
    const float* conv_b  = (const float*)d_in[2];
    const float* query_w = (const float*)d_in[3];
    const float* query_b = (const float*)d_in[4];
    const float* key_w   = (const float*)d_in[5];
    const float* key_b   = (const float*)d_in[6];
    float* out = (float*)d_out;

    cudaFuncSetAttribute(attn_mma_kernel,
                         cudaFuncAttributeMaxDynamicSharedMemorySize, AT_DYN);
    cudaFuncSetAttribute(z_gemm_kernel,
                         cudaFuncAttributeMaxDynamicSharedMemorySize, AT_DYN);
    cudaFuncSetAttribute(gemm_mma_kernel,
                         cudaFuncAttributeMaxDynamicSharedMemorySize, TS_DYN);

    __nv_bfloat16 *wh_p, *wl_p, *wth_p, *wtl_p, *xth_p, *xtl_p;
    cudaGetSymbolAddress((void**)&wh_p, g_wh);
    cudaGetSymbolAddress((void**)&wl_p, g_wl);
    cudaGetSymbolAddress((void**)&wth_p, g_wth);
    cudaGetSymbolAddress((void**)&wtl_p, g_wtl);
    cudaGetSymbolAddress((void**)&xth_p, g_xth);
    cudaGetSymbolAddress((void**)&xtl_p, g_xtl);
    float *x5g_p, *cur_p, *qt_p, *kt_p, *M_p, *u_p, *v_p, *zero_p;
    cudaGetSymbolAddress((void**)&x5g_p, g_x5);
    cudaGetSymbolAddress((void**)&cur_p, g_cur);
    cudaGetSymbolAddress((void**)&qt_p, g_qt);
    cudaGetSymbolAddress((void**)&kt_p, g_kt);
    cudaGetSymbolAddress((void**)&M_p, g_M);
    cudaGetSymbolAddress((void**)&u_p, g_u);
    cudaGetSymbolAddress((void**)&v_p, g_v);
    cudaGetSymbolAddress((void**)&zero_p, g_zero);

    const size_t WSZ = (size_t)CC * CC;
    dim3 xgrid(HWs / 32, CC / 32, BB);      // (18, 24, 16)
    dim3 mgrid(HWs / 96, CC / 128, BB);     // (6, 6, 16)
    dim3 mbgrid(CC / 96, CC / 128, NLAYER); // (8, 6, 4)
    dim3 zgrid(NTOK / 96, CC / 128);        // (96, 6)
    dim3 agrid(NTOK / 128, BB);             // (72, 16)
    dim3 cgrid(BB, HWs / 192);              // (16, 3)
    const int egrid = ELEMS / 256;          // 27648

    // -------- once-per-launch precompute --------
    convert_w_kernel<<<NLAYER * CC * CC / 256, 256>>>(conv_w);
    convert_wt_kernel<<<dim3(24, 24, 8), dim3(32, 8)>>>(query_w, key_w);
    // Mt_i[d][c] = sum_o Wq[o][c] Wk[o][d]:  A = WqT (rows c), B = WkT (rows d)
    //   -> out(R=c, cb=d) written to ft[d*CC + c] = Mt[d][c]
    gemm_mma_kernel<<<mbgrid, 256, TS_DYN>>>(
        wth_p, wtl_p,                                 // A = WqT
        wth_p + NLAYER * WSZ, wtl_p + NLAYER * WSZ,   // B = WkT
        zero_p, nullptr, 0, nullptr, 0, M_p, CC, CC);
    uv_kernel<<<dim3(NLAYER * CC / 8, 2), 256>>>(query_b, key_b);
    convert_x_kernel<<<xgrid, dim3(32, 8)>>>(x5);

    for (int i = 0; i < NLAYER; i++) {
        // x5 = conv(cur) + bias + cur   (fp32 Y + tf32 transposed -> g_kt = keys x)
        gemm_mma_kernel<<<mgrid, 256, TS_DYN>>>(
            wh_p + i * WSZ, wl_p + i * WSZ, xth_p, xtl_p,
            conv_b + i * CC, (i == 0) ? x5 : cur_p, 1,
            x5g_p, 1, kt_p, 0, HWs);
        // queries Z_n = Mt x_n + u -> g_qt
        z_gemm_kernel<<<zgrid, 256, AT_DYN>>>(
            M_p + i * WSZ, kt_p, u_p + i * CC, qt_p);
        // r_n = v . x_n
        r_kernel<<<NTOK / 8, 256>>>(v_p + i * CC);
        attn_mma_kernel<<<agrid, 256, AT_DYN>>>();
        argmax_seeds_kernel<<<BB, 256>>>();
        cor_kernel<<<cgrid, 192>>>();
        minmax_kernel<<<BB, 256>>>();
        apply_t_kernel<<<xgrid, dim3(32, 8)>>>(i > 0 ? 1 : 0);
    }
    consen_kernel<<<CC, 256>>>();
    final_kernel<<<egrid, 256>>>(x5, out);
}

// round 17
// speedup vs baseline: 1.1659x; 1.0433x over previous
#include <cuda_runtime.h>
#include <cuda_bf16.h>
#include <cstdint>

// Problem constants
#define BB   16
#define CC   768
#define HWs  576
#define NTOK (BB*HWs)          // 9216
#define ELEMS (BB*CC*HWs)      // 7,077,888
#define NLAYER 4

// Scratch (device globals; no allocation allowed)
__device__ float g_cur[ELEMS];
__device__ float g_x5[ELEMS];
__device__ float g_qt[(size_t)NTOK*CC];             // QUERIES: Z_n = M^T x_n + u, tf32 [n][d]
__device__ float g_kt[(size_t)NTOK*CC];             // KEYS: x5 transposed, tf32 [n][c]
__device__ __nv_bfloat16 g_xth[(size_t)NTOK*CC];    // layer input transposed hi
__device__ __nv_bfloat16 g_xtl[(size_t)NTOK*CC];    // lo
__device__ __nv_bfloat16 g_wh[(size_t)NLAYER*CC*CC];    // conv weights hi [o][c]
__device__ __nv_bfloat16 g_wl[(size_t)NLAYER*CC*CC];    // lo
__device__ __nv_bfloat16 g_wth[(size_t)2*NLAYER*CC*CC]; // q|k weights TRANSPOSED hi [c][o]
__device__ __nv_bfloat16 g_wtl[(size_t)2*NLAYER*CC*CC]; // lo
__device__ float g_M[(size_t)NLAYER*CC*CC];         // Mt_i[d][c] = sum_o Wq[o][c]Wk[o][d], tf32
__device__ float g_u[NLAYER*CC];                    // Wk^T bq
__device__ float g_v[NLAYER*CC];                    // Wq^T bk
__device__ float g_r[NTOK];                         // v . x_n per token
__device__ float g_zero[CC];                        // stays zero
__device__ float g_maxpart[BB*NTOK];
__device__ float g_seeds[BB*CC];
__device__ float g_cor[BB*HWs];
__device__ float g_consen[CC];

// ============================ PTX helpers (sm_80+ only) =====================
__device__ __forceinline__ uint32_t smem_u32(const void* p) {
    uint32_t a;
    asm("{ .reg .u64 t; cvta.to.shared.u64 t, %1; cvt.u32.u64 %0, t; }" : "=r"(a) : "l"(p));
    return a;
}
__device__ __forceinline__ void cp16(uint32_t d, const void* s) {
    asm volatile("cp.async.cg.shared.global [%0], [%1], 16;" :: "r"(d), "l"(s));
}
__device__ __forceinline__ void cp_commit() { asm volatile("cp.async.commit_group;"); }
template<int N> __device__ __forceinline__ void cp_wait() {
    asm volatile("cp.async.wait_group %0;" :: "n"(N));
}
__device__ __forceinline__ void ldsm4(uint32_t* r, uint32_t a) {
    asm volatile("ldmatrix.sync.aligned.m8n8.x4.shared.b16 {%0,%1,%2,%3}, [%4];"
                 : "=r"(r[0]), "=r"(r[1]), "=r"(r[2]), "=r"(r[3]) : "r"(a));
}
__device__ __forceinline__ void mma16816(float* d, const uint32_t* a, const uint32_t* b) {
    asm volatile("mma.sync.aligned.m16n8k16.row.col.f32.bf16.bf16.f32 "
                 "{%0,%1,%2,%3}, {%4,%5,%6,%7}, {%8,%9}, {%0,%1,%2,%3};"
                 : "+f"(d[0]), "+f"(d[1]), "+f"(d[2]), "+f"(d[3])
                 : "r"(a[0]), "r"(a[1]), "r"(a[2]), "r"(a[3]), "r"(b[0]), "r"(b[1]));
}
__device__ __forceinline__ uint32_t cvt_tf32(float v) {
    uint32_t r;
    asm volatile("cvt.rna.tf32.f32 %0, %1;" : "=r"(r) : "f"(v));
    return r;
}
__device__ __forceinline__ void mma1688_tf32(float* d, const uint32_t* a,
                                             uint32_t b0, uint32_t b1) {
    asm volatile("mma.sync.aligned.m16n8k8.row.col.f32.tf32.tf32.f32 "
                 "{%0,%1,%2,%3}, {%4,%5,%6,%7}, {%8,%9}, {%0,%1,%2,%3};"
                 : "+f"(d[0]), "+f"(d[1]), "+f"(d[2]), "+f"(d[3])
                 : "r"(a[0]), "r"(a[1]), "r"(a[2]), "r"(a[3]), "r"(b0), "r"(b1));
}

// ---- bf16 GEMM stage: 128(A) x 96(B) x 32k, 80B rows ----
#define TS_STAGE 35840
#define TS_DYN   (3*TS_STAGE)    // 107520  (x2 CTAs = 215040 <= 228KB/SM)

// ---- tf32 stage: 128(A) x 96(B) x 32k fp32, 144B rows ----
#define AT_STAGE 32256
#define AT_DYN   (3*AT_STAGE)    // 96768  (x2 CTAs = 193536 <= 228KB/SM)

// ---------------------------------------------------------------------------
// Conv weight conversion: fp32 [o][c] -> bf16 hi/lo.  grid (CC*CC*NLAYER/256).
// ---------------------------------------------------------------------------
__global__ void convert_w_kernel(const float* __restrict__ cw)
{
    const size_t idx = (size_t)blockIdx.x * 256 + threadIdx.x;
    float v = cw[idx];
    __nv_bfloat16 h = __float2bfloat16(v);
    g_wh[idx] = h;
    g_wl[idx] = __float2bfloat16(v - __bfloat162float(h));
}

// ---------------------------------------------------------------------------
// q/k weight transpose+convert: [o][c] fp32 -> [c][o] bf16 hi/lo.
// grid (24, 24, 8): z = which*NLAYER + layer. block (32,8).
// ---------------------------------------------------------------------------
__global__ void convert_wt_kernel(const float* __restrict__ qw,
                                  const float* __restrict__ kw)
{
    __shared__ float tile[32][33];
    const int z = blockIdx.z;
    const int which = z >> 2;            // 0 q, 1 k
    const int layer = z & 3;
    const float* src = (which ? kw : qw) + (size_t)layer * CC * CC;
    __nv_bfloat16* dh = g_wth + (size_t)which * NLAYER * CC * CC;
    __nv_bfloat16* dl = g_wtl + (size_t)which * NLAYER * CC * CC;
    const int c0 = blockIdx.x * 32;
    const int o0 = blockIdx.y * 32;
    const int tx = threadIdx.x, ty = threadIdx.y;

    #pragma unroll
    for (int j = 0; j < 4; j++) {
        int oo = ty * 4 + j;
        tile[oo][tx] = src[(size_t)(o0 + oo) * CC + c0 + tx];
    }
    __syncthreads();
    #pragma unroll
    for (int j = 0; j < 4; j++) {
        int cc = ty * 4 + j;
        float v = tile[tx][cc];          // = src[o0+tx][c0+cc]
        size_t o = ((size_t)layer * CC + c0 + cc) * CC + o0 + tx;
        __nv_bfloat16 h = __float2bfloat16(v);
        dh[o] = h;
        dl[o] = __float2bfloat16(v - __bfloat162float(h));
    }
}

// ---------------------------------------------------------------------------
// Layer-0 input conversion+transpose: ext [b][c][hw] fp32 -> g_xt [n][c] bf16.
// grid (18, 24, 16), block (32,8).
// ---------------------------------------------------------------------------
__global__ void convert_x_kernel(const float* __restrict__ ext)
{
    __shared__ float tile[32][33];
    const int b = blockIdx.z;
    const float* src = ext + (size_t)b * CC * HWs;
    const int hw0 = blockIdx.x * 32;
    const int c0  = blockIdx.y * 32;
    const int tx = threadIdx.x, ty = threadIdx.y;

    #pragma unroll
    for (int j = 0; j < 4; j++) {
        int c = ty * 4 + j;
        tile[c][tx] = src[(size_t)(c0 + c) * HWs + hw0 + tx];
    }
    __syncthreads();
    #pragma unroll
    for (int j = 0; j < 4; j++) {
        int hwl = ty * 4 + j;
        float v = tile[tx][hwl];
        __nv_bfloat16 h = __float2bfloat16(v);
        __nv_bfloat16 l = __float2bfloat16(v - __bfloat162float(h));
        size_t o = (size_t)(b * HWs + hw0 + hwl) * CC + c0 + tx;
        g_xth[o] = h;
        g_xtl[o] = l;
    }
}

// ---------------------------------------------------------------------------
// u/v build, warp-parallel. grid (384, 2), block 256.
// ---------------------------------------------------------------------------
__global__ void uv_kernel(const float* __restrict__ qb, const float* __restrict__ kb)
{
    const int which = blockIdx.y;
    const int idx = blockIdx.x * 8 + (threadIdx.x >> 5);
    const int lane = threadIdx.x & 31;
    const int layer = idx / CC;
    const int c = idx % CC;
    const size_t toff = which ? 0 : (size_t)NLAYER * CC * CC;
    const __nv_bfloat16* th = g_wth + toff + ((size_t)layer * CC + c) * CC;
    const __nv_bfloat16* tl = g_wtl + toff + ((size_t)layer * CC + c) * CC;
    const float* bias = (which ? kb : qb) + layer * CC;
    float s = 0.f;
    for (int o = lane; o < CC; o += 32)
        s = fmaf(__bfloat162float(th[o]) + __bfloat162float(tl[o]), bias[o], s);
    s += __shfl_xor_sync(0xffffffffu, s, 16);
    s += __shfl_xor_sync(0xffffffffu, s, 8);
    s += __shfl_xor_sync(0xffffffffu, s, 4);
    s += __shfl_xor_sync(0xffffffffu, s, 2);
    s += __shfl_xor_sync(0xffffffffu, s, 1);
    if (lane == 0) (which ? g_v : g_u)[idx] = s;
}

// ---------------------------------------------------------------------------
// r_n = v . x_n. grid 1152, block 256 (warp per n).
// ---------------------------------------------------------------------------
__global__ void r_kernel(const float* __restrict__ v)
{
    const int n = blockIdx.x * 8 + (threadIdx.x >> 5);
    const int lane = threadIdx.x & 31;
    const float* x = g_kt + (size_t)n * CC;
    float s = 0.f;
    for (int c = lane; c < CC; c += 32)
        s = fmaf(x[c], v[c], s);
    s += __shfl_xor_sync(0xffffffffu, s, 16);
    s += __shfl_xor_sync(0xffffffffu, s, 8);
    s += __shfl_xor_sync(0xffffffffu, s, 4);
    s += __shfl_xor_sync(0xffffffffu, s, 2);
    s += __shfl_xor_sync(0xffffffffu, s, 1);
    if (lane == 0) g_r[n] = s;
}

// ---------------------------------------------------------------------------
// Split-bf16 mma.sync GEMM, 128 x 96 per CTA, 256 threads, 2 CTAs/SM,
// 3-stage ring, incremental-pointer loader.
// ---------------------------------------------------------------------------
__global__ void __launch_bounds__(256, 2) gemm_mma_kernel(
    const __nv_bfloat16* __restrict__ Ah, const __nv_bfloat16* __restrict__ Al,
    const __nv_bfloat16* __restrict__ Bh, const __nv_bfloat16* __restrict__ Bl,
    const float* __restrict__ bias, const float* __restrict__ resid, int residual,
    float* __restrict__ Y, int write_f32, float* __restrict__ ft,
    int aB, int nB)
{
    extern __shared__ __align__(16) char sm[];
    const int t   = threadIdx.x;
    const int wid = t >> 5;
    const int lid = t & 31;
    const int n0  = blockIdx.x * 96;
    const int m0  = blockIdx.y * 128;
    const int b   = blockIdx.z;
    const int warp_m = wid & 3;
    const int warp_n = wid >> 2;
    const uint32_t smbase = smem_u32(sm);

    // incremental loader state
    const __nv_bfloat16* pAh = Ah + ((size_t)b * aB + m0 + (t >> 2)) * CC + (t & 3) * 8;
    const __nv_bfloat16* pAl = Al + ((size_t)b * aB + m0 + (t >> 2)) * CC + (t & 3) * 8;
    const __nv_bfloat16* pBh = Bh + ((size_t)b * nB + n0 + (t >> 2)) * CC + (t & 3) * 8;
    const __nv_bfloat16* pBl = Bl + ((size_t)b * nB + n0 + (t >> 2)) * CC + (t & 3) * 8;
    const uint32_t aDst = (uint32_t)(t >> 2) * 80u + (uint32_t)(t & 3) * 16u;
    const uint32_t bDst = 20480u + aDst;
    const bool bOK1 = (t < 128);
    int pf_slot = 0;

    auto prefetch = [&]() {
        const uint32_t st = smbase + (uint32_t)pf_slot * TS_STAGE;
        #pragma unroll
        for (int it = 0; it < 2; it++) {
            uint32_t d = st + aDst + (uint32_t)it * (64u * 80u);
            cp16(d,          pAh + it * 64 * CC);
            cp16(d + 10240u, pAl + it * 64 * CC);
        }
        {
            uint32_t d = st + bDst;
            cp16(d,         pBh);
            cp16(d + 7680u, pBl);
        }
        if (bOK1) {
            uint32_t d = st + bDst + (64u * 80u);
            cp16(d,         pBh + 64 * CC);
            cp16(d + 7680u, pBl + 64 * CC);
        }
        cp_commit();
        pf_slot = (pf_slot == 2) ? 0 : pf_slot + 1;
        pAh += 32; pAl += 32; pBh += 32; pBl += 32;
    };

    float acc[2][6][4];
    #pragma unroll
    for (int mt = 0; mt < 2; mt++)
        #pragma unroll
        for (int j = 0; j < 6; j++)
            #pragma unroll
            for (int r = 0; r < 4; r++)
                acc[mt][j][r] = 0.f;

    prefetch(); prefetch();
    int pf = 2;
    int cslot = 0;

    for (int s = 0; s < 24; s++) {
        if (s < 23) cp_wait<1>(); else cp_wait<0>();
        __syncthreads();
        if (pf < 24) { prefetch(); pf++; }

        const uint32_t st = smbase + (uint32_t)cslot * TS_STAGE;
        cslot = (cslot == 2) ? 0 : cslot + 1;
        #pragma unroll
        for (int k16 = 0; k16 < 2; k16++) {
            const int kb = k16 * 16;
            uint32_t bh[12], bl[12];
            #pragma unroll
            for (int nt = 0; nt < 3; nt++) {
                uint32_t ba = st + 20480u
                    + (uint32_t)(warp_n * 48 + nt * 16 + (lid & 7) + ((lid >> 4) & 1) * 8) * 80u
                    + (uint32_t)(kb + ((lid >> 3) & 1) * 8) * 2u;
                ldsm4(&bh[nt * 4], ba);
                ldsm4(&bl[nt * 4], ba + 7680u);
            }
            #pragma unroll
            for (int mt = 0; mt < 2; mt++) {
                uint32_t ah[4], al[4];
                uint32_t aa = st
                    + (uint32_t)(warp_m * 32 + mt * 16 + (lid & 15)) * 80u
                    + (uint32_t)(kb + ((lid >> 4) & 1) * 8) * 2u;
                ldsm4(ah, aa);
                ldsm4(al, aa + 10240u);
                #pragma unroll
                for (int j = 0; j < 6; j++)
                    mma16816(acc[mt][j], ah, &bh[(j >> 1) * 4 + (j & 1) * 2]);
                #pragma unroll
                for (int j = 0; j < 6; j++)
                    mma16816(acc[mt][j], ah, &bl[(j >> 1) * 4 + (j & 1) * 2]);
                #pragma unroll
                for (int j = 0; j < 6; j++)
                    mma16816(acc[mt][j], al, &bh[(j >> 1) * 4 + (j & 1) * 2]);
            }
        }
    }

    // epilogue
    const size_t Yb = (size_t)b * CC * HWs;
    const size_t nb = (size_t)b * nB;
    #pragma unroll
    for (int mt = 0; mt < 2; mt++) {
        int R = m0 + warp_m * 32 + mt * 16 + (lid >> 2);
        float bs0 = bias[R], bs1 = bias[R + 8];
        #pragma unroll
        for (int j = 0; j < 6; j++) {
            int cb = n0 + warp_n * 48 + (j >> 1) * 16 + (j & 1) * 8 + (lid & 3) * 2;
            float v00 = acc[mt][j][0] + bs0, v01 = acc[mt][j][1] + bs0;
            float v10 = acc[mt][j][2] + bs1, v11 = acc[mt][j][3] + bs1;
            if (residual) {
                size_t a0 = Yb + (size_t)R * HWs + cb;
                size_t a1 = a0 + 8 * HWs;
                float2 r0 = *(const float2*)(resid + a0);
                float2 r1 = *(const float2*)(resid + a1);
                v00 += r0.x; v01 += r0.y; v10 += r1.x; v11 += r1.y;
            }
            if (write_f32) {
                size_t a0 = Yb + (size_t)R * HWs + cb;
                size_t a1 = a0 + 8 * HWs;
                *(float2*)(Y + a0) = make_float2(v00, v01);
                *(float2*)(Y + a1) = make_float2(v10, v11);
            }
            if (ft) {
                size_t r0o = (nb + cb) * CC;
                size_t r1o = r0o + CC;
                ft[r0o + R]     = __uint_as_float(cvt_tf32(v00));
                ft[r1o + R]     = __uint_as_float(cvt_tf32(v01));
                ft[r0o + R + 8] = __uint_as_float(cvt_tf32(v10));
                ft[r1o + R + 8] = __uint_as_float(cvt_tf32(v11));
            }
        }
    }
}

// ---------------------------------------------------------------------------
// Z GEMM (tf32 1-pass): Z[n][d] = sum_c Mt[d][c] x_n[c] + u[d]  (queries).
// Incremental-pointer loader. grid (96, 6), 256 thr.
// ---------------------------------------------------------------------------
__global__ void __launch_bounds__(256, 2) z_gemm_kernel(
    const float* __restrict__ A, const float* __restrict__ B,
    const float* __restrict__ bias, float* __restrict__ ft)
{
    extern __shared__ __align__(16) char sm[];
    const int t   = threadIdx.x;
    const int wid = t >> 5;
    const int lid = t & 31;
    const int n0  = blockIdx.x * 96;
    const int m0  = blockIdx.y * 128;
    const int warp_m = wid & 3;
    const int warp_n = wid >> 2;
    const uint32_t smbase = smem_u32(sm);

    uint32_t a_off[2];
    #pragma unroll
    for (int mt = 0; mt < 2; mt++)
        a_off[mt] = (uint32_t)(warp_m * 32 + mt * 16 + ((lid >> 3) & 1) * 8 + (lid & 7)) * 144u
                  + (uint32_t)((lid >> 4) & 1) * 16u;
    uint32_t b_off[3];
    #pragma unroll
    for (int p = 0; p < 3; p++)
        b_off[p] = 18432u
                 + (uint32_t)(warp_n * 48 + (2 * p + ((lid >> 4) & 1)) * 8 + (lid & 7)) * 144u
                 + (uint32_t)((lid >> 3) & 1) * 16u;

    const float* pA = A + (size_t)(m0 + (t >> 3)) * CC + (t & 7) * 4;
    const float* pB = B + (size_t)(n0 + (t >> 3)) * CC + (t & 7) * 4;
    const uint32_t aDst = (uint32_t)(t >> 3) * 144u + (uint32_t)(t & 7) * 16u;
    const uint32_t bDst = 18432u + aDst;
    int pf_slot = 0;

    auto prefetch = [&]() {
        const uint32_t st = smbase + (uint32_t)pf_slot * AT_STAGE;
        #pragma unroll
        for (int it = 0; it < 4; it++)
            cp16(st + aDst + (uint32_t)it * (32u * 144u), pA + it * 32 * CC);
        #pragma unroll
        for (int it = 0; it < 3; it++)
            cp16(st + bDst + (uint32_t)it * (32u * 144u), pB + it * 32 * CC);
        cp_commit();
        pf_slot = (pf_slot == 2) ? 0 : pf_slot + 1;
        pA += 32; pB += 32;
    };

    float acc[2][6][4];
    #pragma unroll
    for (int mt = 0; mt < 2; mt++)
        #pragma unroll
        for (int j = 0; j < 6; j++)
            #pragma unroll
            for (int r = 0; r < 4; r++)
                acc[mt][j][r] = 0.f;

    prefetch(); prefetch();
    int pf = 2;
    int cslot = 0;

    for (int s = 0; s < 24; s++) {
        if (s < 23) cp_wait<1>(); else cp_wait<0>();
        __syncthreads();
        if (pf < 24) { prefetch(); pf++; }

        const uint32_t st = smbase + (uint32_t)cslot * AT_STAGE;
        cslot = (cslot == 2) ? 0 : cslot + 1;
        #pragma unroll
        for (int k8 = 0; k8 < 4; k8++) {
            const uint32_t kbyte = (uint32_t)k8 * 32u;
            uint32_t bf[12];
            #pragma unroll
            for (int p = 0; p < 3; p++)
                ldsm4(&bf[p * 4], st + b_off[p] + kbyte);
            #pragma unroll
            for (int mt = 0; mt < 2; mt++) {
                uint32_t af[4];
                ldsm4(af, st + a_off[mt] + kbyte);
                #pragma unroll
                for (int nt = 0; nt < 6; nt++)
                    mma1688_tf32(acc[mt][nt], af, bf[2 * nt], bf[2 * nt + 1]);
            }
        }
    }

    #pragma unroll
    for (int mt = 0; mt < 2; mt++) {
        int R = m0 + warp_m * 32 + mt * 16 + (lid >> 2);
        float u0 = bias[R], u1 = bias[R + 8];
        #pragma unroll
        for (int j = 0; j < 6; j++) {
            int cb = n0 + warp_n * 48 + j * 8 + (lid & 3) * 2;
            size_t r0o = (size_t)cb * CC;
            size_t r1o = r0o + CC;
            ft[r0o + R]     = __uint_as_float(cvt_tf32(acc[mt][j][0] + u0));
            ft[r1o + R]     = __uint_as_float(cvt_tf32(acc[mt][j][1] + u0));
            ft[r0o + R + 8] = __uint_as_float(cvt_tf32(acc[mt][j][2] + u1));
            ft[r1o + R + 8] = __uint_as_float(cvt_tf32(acc[mt][j][3] + u1));
        }
    }
}

// ---------------------------------------------------------------------------
// tf32 attention row-max, ldmatrix fragments, incremental-pointer loader,
// nested (ct, k) loops. Queries = g_qt (Z), keys = g_kt (x).
// grid (72 m-tiles, 16 bk).
// ---------------------------------------------------------------------------
__global__ void __launch_bounds__(256, 2) attn_mma_kernel()
{
    extern __shared__ __align__(16) char sm[];
    __shared__ float srow[2][128];

    const int t   = threadIdx.x;
    const int wid = t >> 5;
    const int lid = t & 31;
    const int n0  = blockIdx.x * 128;
    const int bk  = blockIdx.y;
    const int warp_m = wid & 3;
    const int warp_n = wid >> 2;
    const uint32_t smbase = smem_u32(sm);

    uint32_t a_off[2];
    #pragma unroll
    for (int mt = 0; mt < 2; mt++)
        a_off[mt] = (uint32_t)(warp_m * 32 + mt * 16 + ((lid >> 3) & 1) * 8 + (lid & 7)) * 144u
                  + (uint32_t)((lid >> 4) & 1) * 16u;
    uint32_t b_off[3];
    #pragma unroll
    for (int p = 0; p < 3; p++)
        b_off[p] = 18432u
                 + (uint32_t)(warp_n * 48 + (2 * p + ((lid >> 4) & 1)) * 8 + (lid & 7)) * 144u
                 + (uint32_t)((lid >> 3) & 1) * 16u;

    // incremental loader state
    const float* pA = g_qt + (size_t)(n0 + (t >> 3)) * CC + (t & 7) * 4;
    const float* pB = g_kt + (size_t)(bk * HWs + (t >> 3)) * CC + (t & 7) * 4;
    const uint32_t aDst = (uint32_t)(t >> 3) * 144u + (uint32_t)(t & 7) * 16u;
    const uint32_t bDst = 18432u + aDst;
    int pf_slot = 0, pf_kk = 0;

    auto prefetch = [&]() {
        const uint32_t st = smbase + (uint32_t)pf_slot * AT_STAGE;
        #pragma unroll
        for (int it = 0; it < 4; it++)
            cp16(st + aDst + (uint32_t)it * (32u * 144u), pA + it * 32 * CC);
        #pragma unroll
        for (int it = 0; it < 3; it++)
            cp16(st + bDst + (uint32_t)it * (32u * 144u), pB + it * 32 * CC);
        cp_commit();
        pf_slot = (pf_slot == 2) ? 0 : pf_slot + 1;
        pA += 32; pB += 32;
        if (++pf_kk == 24) { pf_kk = 0; pA -= 768; pB += 96 * CC - 768; }
    };

    float acc[2][6][4];
    float rm[2][2] = {{-3.402823e38f, -3.402823e38f}, {-3.402823e38f, -3.402823e38f}};

    prefetch(); prefetch();
    int pf = 2;
    int cslot = 0;

    for (int ct = 0; ct < 6; ct++) {
        #pragma unroll
        for (int mt = 0; mt < 2; mt++)
            #pragma unroll
            for (int j = 0; j < 6; j++)
                #pragma unroll
                for (int r = 0; r < 4; r++)
                    acc[mt][j][r] = 0.f;

        for (int k = 0; k < 24; k++) {
            if (pf < 144) cp_wait<1>(); else cp_wait<0>();
            __syncthreads();
            if (pf < 144) { prefetch(); pf++; }

            const uint32_t st = smbase + (uint32_t)cslot * AT_STAGE;
            cslot = (cslot == 2) ? 0 : cslot + 1;
            #pragma unroll
            for (int k8 = 0; k8 < 4; k8++) {
                const uint32_t kbyte = (uint32_t)k8 * 32u;
                uint32_t bf[12];
                #pragma unroll
                for (int p = 0; p < 3; p++)
                    ldsm4(&bf[p * 4], st + b_off[p] + kbyte);
                #pragma unroll
                for (int mt = 0; mt < 2; mt++) {
                    uint32_t af[4];
                    ldsm4(af, st + a_off[mt] + kbyte);
                    #pragma unroll
                    for (int nt = 0; nt < 6; nt++)
                        mma1688_tf32(acc[mt][nt], af, bf[2 * nt], bf[2 * nt + 1]);
                }
            }
        }

        // ct-tile epilogue: fold into running row max
        #pragma unroll
        for (int mt = 0; mt < 2; mt++) {
            float m0 = -3.402823e38f, m1 = -3.402823e38f;
            #pragma unroll
            for (int j = 0; j < 6; j++) {
                m0 = fmaxf(m0, fmaxf(acc[mt][j][0], acc[mt][j][1]));
                m1 = fmaxf(m1, fmaxf(acc[mt][j][2], acc[mt][j][3]));
            }
            m0 = fmaxf(m0, __shfl_xor_sync(0xffffffffu, m0, 1));
            m0 = fmaxf(m0, __shfl_xor_sync(0xffffffffu, m0, 2));
            m1 = fmaxf(m1, __shfl_xor_sync(0xffffffffu, m1, 1));
            m1 = fmaxf(m1, __shfl_xor_sync(0xffffffffu, m1, 2));
            rm[mt][0] = fmaxf(rm[mt][0], m0);
            rm[mt][1] = fmaxf(rm[mt][1], m1);
        }
    }

    __syncthreads();
    if ((lid & 3) == 0) {
        #pragma unroll
        for (int mt = 0; mt < 2; mt++) {
            int r = warp_m * 32 + mt * 16 + (lid >> 2);
            srow[warp_n][r]     = rm[mt][0];
            srow[warp_n][r + 8] = rm[mt][1];
        }
    }
    __syncthreads();
    if (t < 128)
        g_maxpart[bk * NTOK + n0 + t] = fmaxf(srow[0][t], srow[1][t]);
}

// ---------------------------------------------------------------------------
// argmax over hw of [16*r_n + sum_bk maxpart], then seeds. grid=16, block 256.
// ---------------------------------------------------------------------------
__global__ void argmax_seeds_kernel()
{
    const int b = blockIdx.x;
    const int tid = threadIdx.x;
    __shared__ float sv[256];
    __shared__ int   si[256];
    __shared__ int   s_hw;
    __shared__ float s_inv;

    float best = -3.402823e38f;
    int   bidx = 0;
    for (int hw = tid; hw < HWs; hw += 256) {
        float s = 16.f * g_r[b * HWs + hw];
        #pragma unroll
        for (int bk = 0; bk < BB; bk++)
            s += g_maxpart[bk * NTOK + b * HWs + hw];
        if (s > best) { best = s; bidx = hw; }
    }
    sv[tid] = best; si[tid] = bidx;
    __syncthreads();
    for (int s = 128; s > 0; s >>= 1) {
        if (tid < s) {
            if (sv[tid + s] > sv[tid] ||
                (sv[tid + s] == sv[tid] && si[tid + s] < si[tid])) {
                sv[tid] = sv[tid + s];
                si[tid] = si[tid + s];
            }
        }
        __syncthreads();
    }
    if (tid == 0) s_hw = si[0];
    __syncthreads();

    const int hws = s_hw;
    float vv[3];
    float sq = 0.f;
    #pragma unroll
    for (int j = 0; j < 3; j++) {
        int c = tid + j * 256;
        vv[j] = g_x5[(size_t)b * CC * HWs + (size_t)c * HWs + hws];
        sq = fmaf(vv[j], vv[j], sq);
    }
    sv[tid] = sq;
    __syncthreads();
    for (int s = 128; s > 0; s >>= 1) {
        if (tid < s) sv[tid] += sv[tid + s];
        __syncthreads();
    }
    if (tid == 0) s_inv = 1.f / fmaxf(sqrtf(sv[0]), 1e-12f);
    __syncthreads();
    float inv = s_inv;
    #pragma unroll
    for (int j = 0; j < 3; j++)
        g_seeds[b * CC + tid + j * 256] = vv[j] * inv;
}

// ---------------------------------------------------------------------------
// cor[b,hw] = (1/16) * sum_{b'} relu(x5[b,:,hw] . seeds[b',:]) / ||x5[b,:,hw]||
// grid=(16,3), block=192.
// ---------------------------------------------------------------------------
__global__ void cor_kernel()
{
    __shared__ float ss[BB * CC];
    const int b = blockIdx.x;
    for (int i = threadIdx.x; i < BB * CC; i += blockDim.x) ss[i] = g_seeds[i];
    __syncthreads();

    const int hw = blockIdx.y * 192 + threadIdx.x;
    const float* xp = g_x5 + (size_t)b * CC * HWs + hw;
    float acc[BB] = {};
    float sq = 0.f;
    for (int c = 0; c < CC; c++) {
        float v = xp[(size_t)c * HWs];
        sq = fmaf(v, v, sq);
        #pragma unroll
        for (int o = 0; o < BB; o++)
            acc[o] = fmaf(v, ss[o * CC + c], acc[o]);
    }
    float s = 0.f;
    #pragma unroll
    for (int o = 0; o < BB; o++) s += fmaxf(acc[o], 0.f);
    float nrm = fmaxf(sqrtf(sq), 1e-12f);
    g_cor[b * HWs + hw] = s / (16.f * nrm);
}

// Per-batch min-max normalize of cor. grid=16, block=256.
__global__ void minmax_kernel()
{
    const int b = blockIdx.x;
    const int tid = threadIdx.x;
    __shared__ float smn[256], smx[256];
    float mn = 3.402823e38f, mx = -3.402823e38f;
    for (int hw = tid; hw < HWs; hw += 256) {
        float v = g_cor[b * HWs + hw];
        mn = fminf(mn, v);
        mx = fmaxf(mx, v);
    }
    smn[tid] = mn; smx[tid] = mx;
    __syncthreads();
    for (int s = 128; s > 0; s >>= 1) {
        if (tid < s) {
            smn[tid] = fminf(smn[tid], smn[tid + s]);
            smx[tid] = fmaxf(smx[tid], smx[tid + s]);
        }
        __syncthreads();
    }
    float m0 = smn[0];
    float inv = 1.f / (smx[0] - m0 + 1e-12f);
    for (int hw = tid; hw < HWs; hw += 256)
        g_cor[b * HWs + hw] = (g_cor[b * HWs + hw] - m0) * inv;
}

// ---------------------------------------------------------------------------
// apply + transpose-convert. grid (18, 24, 16), block (32,8).
// ---------------------------------------------------------------------------
__global__ void apply_t_kernel(int add_prev)
{
    __shared__ float tile[32][33];
    const int b = blockIdx.z;
    const int hw0 = blockIdx.x * 32;
    const int c0  = blockIdx.y * 32;
    const int tx = threadIdx.x, ty = threadIdx.y;

    const float corv = g_cor[b * HWs + hw0 + tx];
    const size_t base = (size_t)b * CC * HWs;

    #pragma unroll
    for (int j = 0; j < 4; j++) {
        int c = c0 + ty * 4 + j;
        size_t idx = base + (size_t)c * HWs + hw0 + tx;
        float v = g_x5[idx] * corv;
        if (add_prev) v += g_cur[idx];
        g_cur[idx] = v;
        tile[ty * 4 + j][tx] = v;
    }
    __syncthreads();
    #pragma unroll
    for (int j = 0; j < 4; j++) {
        int hwl = ty * 4 + j;
        float v = tile[tx][hwl];
        __nv_bfloat16 h = __float2bfloat16(v);
        __nv_bfloat16 l = __float2bfloat16(v - __bfloat162float(h));
        size_t o = (size_t)(b * HWs + hw0 + hwl) * CC + c0 + tx;
        g_xth[o] = h;
        g_xtl[o] = l;
    }
}

// consen[c] = mean over (b,hw) of cur. grid=768, block=256.
__global__ void consen_kernel()
{
    const int c = blockIdx.x;
    const int tid = threadIdx.x;
    __shared__ float sm[256];
    float s = 0.f;
    for (int b = 0; b < BB; b++) {
        const float* p = g_cur + (size_t)b * CC * HWs + (size_t)c * HWs;
        for (int hw = tid; hw < HWs; hw += 256) s += p[hw];
    }
    sm[tid] = s;
    __syncthreads();
    for (int st = 128; st > 0; st >>= 1) {
        if (tid < st) sm[tid] += sm[tid + st];
        __syncthreads();
    }
    if (tid == 0) g_consen[c] = sm[0] * (1.f / (float)(BB * HWs));
}

__global__ void final_kernel(const float* __restrict__ xin, float* __restrict__ out)
{
    int idx = blockIdx.x * 256 + threadIdx.x;
    int c = (idx / HWs) % CC;
    out[idx] = g_cur[idx] + xin[idx] * g_consen[c];
}

// ---------------------------------------------------------------------------
extern "C" void kernel_launch(void* const* d_in, const int* in_sizes, int n_in,
                              void* d_out, int out_size)
{
    const float* x5      = (const float*)d_in[0];
    const float* conv_w  = (const float*)d_in[1];
    const float* conv_b  = (const float*)d_in[2];
    const float* query_w = (const float*)d_in[3];
    const float* query_b = (const float*)d_in[4];
    const float* key_w   = (const float*)d_in[5];
    const float* key_b   = (const float*)d_in[6];
    float* out = (float*)d_out;

    cudaFuncSetAttribute(attn_mma_kernel,
                         cudaFuncAttributeMaxDynamicSharedMemorySize, AT_DYN);
    cudaFuncSetAttribute(z_gemm_kernel,
                         cudaFuncAttributeMaxDynamicSharedMemorySize, AT_DYN);
    cudaFuncSetAttribute(gemm_mma_kernel,
                         cudaFuncAttributeMaxDynamicSharedMemorySize, TS_DYN);

    __nv_bfloat16 *wh_p, *wl_p, *wth_p, *wtl_p, *xth_p, *xtl_p;
    cudaGetSymbolAddress((void**)&wh_p, g_wh);
    cudaGetSymbolAddress((void**)&wl_p, g_wl);
    cudaGetSymbolAddress((void**)&wth_p, g_wth);
    cudaGetSymbolAddress((void**)&wtl_p, g_wtl);
    cudaGetSymbolAddress((void**)&xth_p, g_xth);
    cudaGetSymbolAddress((void**)&xtl_p, g_xtl);
    float *x5g_p, *cur_p, *qt_p, *kt_p, *M_p, *u_p, *v_p, *zero_p;
    cudaGetSymbolAddress((void**)&x5g_p, g_x5);
    cudaGetSymbolAddress((void**)&cur_p, g_cur);
    cudaGetSymbolAddress((void**)&qt_p, g_qt);
    cudaGetSymbolAddress((void**)&kt_p, g_kt);
    cudaGetSymbolAddress((void**)&M_p, g_M);
    cudaGetSymbolAddress((void**)&u_p, g_u);
    cudaGetSymbolAddress((void**)&v_p, g_v);
    cudaGetSymbolAddress((void**)&zero_p, g_zero);

    const size_t WSZ = (size_t)CC * CC;
    dim3 xgrid(HWs / 32, CC / 32, BB);      // (18, 24, 16)
    dim3 mgrid(HWs / 96, CC / 128, BB);     // (6, 6, 16)
    dim3 mbgrid(CC / 96, CC / 128, NLAYER); // (8, 6, 4)
    dim3 zgrid(NTOK / 96, CC / 128);        // (96, 6)
    dim3 agrid(NTOK / 128, BB);             // (72, 16)
    dim3 cgrid(BB, HWs / 192);              // (16, 3)
    const int egrid = ELEMS / 256;          // 27648

    // -------- once-per-launch precompute --------
    convert_w_kernel<<<NLAYER * CC * CC / 256, 256>>>(conv_w);
    convert_wt_kernel<<<dim3(24, 24, 8), dim3(32, 8)>>>(query_w, key_w);
    // Mt_i[d][c] = sum_o Wq[o][c] Wk[o][d]:  A = WqT (rows c), B = WkT (rows d)
    gemm_mma_kernel<<<mbgrid, 256, TS_DYN>>>(
        wth_p, wtl_p,
        wth_p + NLAYER * WSZ, wtl_p + NLAYER * WSZ,
        zero_p, nullptr, 0, nullptr, 0, M_p, CC, CC);
    uv_kernel<<<dim3(NLAYER * CC / 8, 2), 256>>>(query_b, key_b);
    convert_x_kernel<<<xgrid, dim3(32, 8)>>>(x5);

    for (int i = 0; i < NLAYER; i++) {
        // x5 = conv(cur) + bias + cur   (fp32 Y + tf32 transposed -> g_kt = keys x)
        gemm_mma_kernel<<<mgrid, 256, TS_DYN>>>(
            wh_p + i * WSZ, wl_p + i * WSZ, xth_p, xtl_p,
            conv_b + i * CC, (i == 0) ? x5 : cur_p, 1,
            x5g_p, 1, kt_p, 0, HWs);
        // queries Z_n = Mt x_n + u -> g_qt
        z_gemm_kernel<<<zgrid, 256, AT_DYN>>>(
            M_p + i * WSZ, kt_p, u_p + i * CC, qt_p);
        // r_n = v . x_n
        r_kernel<<<NTOK / 8, 256>>>(v_p + i * CC);
        attn_mma_kernel<<<agrid, 256, AT_DYN>>>();
        argmax_seeds_kernel<<<BB, 256>>>();
        cor_kernel<<<cgrid, 192>>>();
        minmax_kernel<<<BB, 256>>>();
        apply_t_kernel<<<xgrid, dim3(32, 8)>>>(i > 0 ? 1 : 0);
    }
    consen_kernel<<<CC, 256>>>();
    final_kernel<<<egrid, 256>>>(x5, out);
}